// round 14
// baseline (speedup 1.0000x reference)
#include <cuda_runtime.h>
#include <cuda_fp16.h>
#include <mma.h>
#include <math.h>
#include <stdint.h>

using namespace nvcuda;

#define BB   2
#define SS   8192
#define DD   1024
#define NWIN 7
#define NBW  14
#define WLEN 2048
#define GG   128

// ---------------- static scratch ----------------
__device__ __half g_xh    [(size_t)BB * SS * DD];
__device__ __half g_Wc2h  [(size_t)DD * 4096];
__device__ __half g_gth   [(size_t)BB * 256 * DD];
__device__ __half g_lg2h  [(size_t)BB * SS * 256];
__device__ __half g_Ph    [(size_t)NBW * WLEN * WLEN];
__device__ __half g_localh[(size_t)BB * SS * DD];
__device__ __half g_globh [(size_t)BB * SS * DD];
__device__ __half g_mixedh[(size_t)BB * SS * DD];
__device__ __half g_Wmh   [(size_t)DD * 2 * DD];
__device__ __half g_Woh   [(size_t)DD * DD];
__device__ __half g_Ddh   [(size_t)BB * 8 * 1024 * 1024];
__device__ __half g_Doh   [(size_t)BB * 7 * 1024 * 1024];
__device__ __half g_Oscrh [(size_t)NBW * WLEN * DD];
__device__ float  g_lg2   [(size_t)BB * SS * 256];
__device__ float  g_xt    [(size_t)BB * DD * SS];
__device__ float  g_bcast [(size_t)BB * SS * DD];

struct GP {
    const __half* A;
    const __half* A2;
    const __half* B;
    float*  Cf;
    __half* Ch;
    __half* Ch2;          // mode-4 off-diag target
    const float* bias;    // per-column bias
    // mixEpi inputs
    const __half* mixLoc;
    const __half* mixGlob;
    const float*  mixBcast;
    int lda, ldb, ldc;
    long sA, sB, sC;
    int K, kSplit;
    float alpha;
    int mode;             // 0 normal, 4 combined scores
    int winB;
    int causal, klimit;
    int mixEpi;           // epilogue: sigmoid gate mix
};

__device__ __forceinline__ long window_off(int z) {
    return (long)(z / NWIN) * ((long)SS * DD) + (long)(z % NWIN) * (1024L * DD);
}

__device__ __forceinline__ void cp16(void* smem, const void* g) {
    uint32_t s = (uint32_t)__cvta_generic_to_shared(smem);
    asm volatile("cp.async.ca.shared.global [%0], [%1], 16;\n" :: "r"(s), "l"(g));
}
__device__ __forceinline__ void cp_commit() { asm volatile("cp.async.commit_group;\n"); }
template<int N> __device__ __forceinline__ void cp_wait() { asm volatile("cp.async.wait_group %0;\n" :: "n"(N)); }

// TB=1: C = A*B^T ; TB=0: C = A*B. fp16 operands, fp32 accumulate.
template<int TB>
__global__ void __launch_bounds__(128) gemm_h(GP p) {
    constexpr int BM = 128, BN = 128, BK = 32, ST = 4;
    constexpr int ALD = 40;
    constexpr int BLD = TB ? 40 : 136;
    constexpr int BROWS = TB ? 128 : 32;
    constexpr int ASTG = BM * ALD;
    constexpr int BSTG = BROWS * BLD;

    int i0 = blockIdx.y * BM;
    int j0 = blockIdx.x * BN;
    if (p.causal && j0 > i0) return;
    int z = blockIdx.z;
    const __half* A;
    const __half* Bm;
    __half* ChBase = p.Ch;
    int zc = z;
    if (p.mode == 4) {
        if (z < BB * 8) {
            if (j0 > i0) return;
            long o = (long)(z >> 3) * ((long)SS * DD) + (long)(z & 7) * (1024L * DD);
            A = p.A + o; Bm = p.B + o;
        } else {
            int zz = z - BB * 8;
            int b = zz / 7, n = zz % 7;
            A  = p.A + (long)b * ((long)SS * DD) + (long)(n + 1) * (1024L * DD);
            Bm = p.B + (long)b * ((long)SS * DD) + (long)n * (1024L * DD);
            ChBase = p.Ch2; zc = zz;
        }
    }
    else { A = p.A + z * p.sA; Bm = p.B + (p.winB ? window_off(z) : z * p.sB); }
    float*  Cf = p.Cf ? p.Cf + z * p.sC : nullptr;
    __half* Ch = ChBase ? ChBase + zc * p.sC : nullptr;
    int K  = p.klimit ? min(p.K, i0 + BM) : p.K;
    int KT = K / BK;

    extern __shared__ __half smem_h[];
    __half* Asm = smem_h;
    __half* Bsm = smem_h + ST * ASTG;

    int tid = threadIdx.x;
    int ar = tid >> 2, ac = (tid & 3) << 3;
    int br, bcd;
    if (TB) { br = tid >> 2;  bcd = (tid & 3) << 3;  }
    else    { br = tid >> 4;  bcd = (tid & 15) << 3; }

    auto load_tile = [&](int kt, int sl) {
        long acol = (long)kt * BK;
        const __half* Ag;
        if (p.A2 && acol >= p.kSplit)
            Ag = p.A2 + (long)(i0 + ar) * p.lda + (acol - p.kSplit) + ac;
        else
            Ag = A + (long)(i0 + ar) * p.lda + acol + ac;
        __half* As = Asm + sl * ASTG;
        #pragma unroll
        for (int q = 0; q < 4; q++)
            cp16(&As[(ar + 32 * q) * ALD + ac], Ag + (long)(32 * q) * p.lda);
        __half* Bs = Bsm + sl * BSTG;
        if (TB) {
            const __half* Bg = Bm + (long)(j0 + br) * p.ldb + acol + bcd;
            #pragma unroll
            for (int q = 0; q < 4; q++)
                cp16(&Bs[(br + 32 * q) * BLD + bcd], Bg + (long)(32 * q) * p.ldb);
        } else {
            const __half* Bg = Bm + (acol + br) * (long)p.ldb + j0 + bcd;
            #pragma unroll
            for (int q = 0; q < 4; q++)
                cp16(&Bs[(br + 8 * q) * BLD + bcd], Bg + (long)(8 * q) * p.ldb);
        }
    };

    #pragma unroll
    for (int s = 0; s < ST - 1; s++) {
        if (s < KT) load_tile(s, s);
        cp_commit();
    }

    int wid = tid >> 5;
    int lane = tid & 31;
    int wr  = (wid & 1) * 64;
    int wc  = (wid >> 1) * 64;

    wmma::fragment<wmma::accumulator, 16, 16, 16, float> acc[4][4];
    #pragma unroll
    for (int i = 0; i < 4; i++)
        #pragma unroll
        for (int j = 0; j < 4; j++) wmma::fill_fragment(acc[i][j], 0.0f);

    for (int kt = 0; kt < KT; kt++) {
        cp_wait<ST - 2>();
        __syncthreads();
        if (kt + ST - 1 < KT) load_tile(kt + ST - 1, (kt + ST - 1) & (ST - 1));
        cp_commit();

        int sl = kt & (ST - 1);
        const __half* As = Asm + sl * ASTG;
        const __half* Bs = Bsm + sl * BSTG;

        #pragma unroll
        for (int ks = 0; ks < 2; ks++) {
            wmma::fragment<wmma::matrix_a, 16, 16, 16, __half, wmma::row_major> af[4];
            #pragma unroll
            for (int i = 0; i < 4; i++)
                wmma::load_matrix_sync(af[i], &As[(wr + i * 16) * ALD + ks * 16], ALD);
            #pragma unroll
            for (int j = 0; j < 4; j++) {
                if (TB) {
                    wmma::fragment<wmma::matrix_b, 16, 16, 16, __half, wmma::col_major> bf;
                    wmma::load_matrix_sync(bf, &Bs[(wc + j * 16) * BLD + ks * 16], BLD);
                    #pragma unroll
                    for (int i = 0; i < 4; i++)
                        wmma::mma_sync(acc[i][j], af[i], bf, acc[i][j]);
                } else {
                    wmma::fragment<wmma::matrix_b, 16, 16, 16, __half, wmma::row_major> bf;
                    wmma::load_matrix_sync(bf, &Bs[(ks * 16) * BLD + wc + j * 16], BLD);
                    #pragma unroll
                    for (int i = 0; i < 4; i++)
                        wmma::mma_sync(acc[i][j], af[i], bf, acc[i][j]);
                }
            }
        }
    }

    // ---- staged epilogue ----
    __syncthreads();
    float* stg = reinterpret_cast<float*>(smem_h) + wid * (64 * 72);
    #pragma unroll
    for (int i = 0; i < 4; i++)
        #pragma unroll
        for (int j = 0; j < 4; j++)
            wmma::store_matrix_sync(&stg[(i * 16) * 72 + j * 16], acc[i][j], 72, wmma::mem_row_major);
    __syncwarp();

    int rbase = i0 + wr;
    int cbase = j0 + wc;
    #pragma unroll
    for (int rr = 0; rr < 64; rr += 8) {
        int r = rr + (lane >> 2);
        int c = (lane & 3) << 4;
        long gro = (long)(rbase + r) * p.ldc + cbase + c;
        #pragma unroll
        for (int q = 0; q < 4; q++) {
            float4 v = *(float4*)&stg[r * 72 + c + q * 4];
            v.x *= p.alpha; v.y *= p.alpha; v.z *= p.alpha; v.w *= p.alpha;
            if (p.bias) {
                float4 b = *(const float4*)&p.bias[cbase + c + q * 4];
                v.x += b.x; v.y += b.y; v.z += b.z; v.w += b.w;
            }
            if (p.mixEpi) {
                // v = gate logits; mixed = sigmoid(v)*local + (1-sig)*glob + bcast
                float2 l0 = __half22float2(*(const __half2*)&p.mixLoc[gro + q * 4]);
                float2 l1 = __half22float2(*(const __half2*)&p.mixLoc[gro + q * 4 + 2]);
                float2 g0 = __half22float2(*(const __half2*)&p.mixGlob[gro + q * 4]);
                float2 g1 = __half22float2(*(const __half2*)&p.mixGlob[gro + q * 4 + 2]);
                float4 bc = *(const float4*)&p.mixBcast[gro + q * 4];
                float s0 = 1.0f / (1.0f + __expf(-v.x));
                float s1 = 1.0f / (1.0f + __expf(-v.y));
                float s2v = 1.0f / (1.0f + __expf(-v.z));
                float s3 = 1.0f / (1.0f + __expf(-v.w));
                v.x = s0 * l0.x + (1.0f - s0) * g0.x + bc.x;
                v.y = s1 * l0.y + (1.0f - s1) * g0.y + bc.y;
                v.z = s2v * l1.x + (1.0f - s2v) * g1.x + bc.z;
                v.w = s3 * l1.y + (1.0f - s3) * g1.y + bc.w;
            }
            if (Cf) *(float4*)&Cf[gro + q * 4] = v;
            if (Ch) {
                *(__half2*)&Ch[gro + q * 4]     = __floats2half2_rn(v.x, v.y);
                *(__half2*)&Ch[gro + q * 4 + 2] = __floats2half2_rn(v.z, v.w);
            }
        }
    }
}

#define SMEM_TB1 ((4 * (128 * 40) + 4 * (128 * 40)) * 2)
#define SMEM_TB0 ((4 * (128 * 40) + 4 * (32 * 136)) * 2)

// ---------------- elementwise ----------------
__global__ void prep_x(const float* __restrict__ x, __half* __restrict__ xh, float* __restrict__ xt) {
    __shared__ float t[32][33];
    int b = blockIdx.z;
    long bo = (long)b * SS * DD;
    int s0 = blockIdx.y * 32, d0 = blockIdx.x * 32;
    int tx = threadIdx.x, ty = threadIdx.y;
    #pragma unroll
    for (int k = 0; k < 32; k += 8) {
        long gi = bo + (long)(s0 + ty + k) * DD + d0 + tx;
        float v = x[gi];
        t[ty + k][tx] = v;
        xh[gi] = __float2half(v);
    }
    __syncthreads();
    #pragma unroll
    for (int k = 0; k < 32; k += 8)
        xt[(long)b * DD * SS + (long)(d0 + ty + k) * SS + s0 + tx] = t[tx][ty + k];
}

// transpose (b, d, s) -> (b, s, d)
__global__ void transpose_back(const float* __restrict__ xt, float* __restrict__ bc) {
    __shared__ float t[32][33];
    int b = blockIdx.z;
    int s0 = blockIdx.x * 32, d0 = blockIdx.y * 32;
    int tx = threadIdx.x, ty = threadIdx.y;
    #pragma unroll
    for (int k = 0; k < 32; k += 8)
        t[ty + k][tx] = xt[(long)b * DD * SS + (long)(d0 + ty + k) * SS + s0 + tx];
    __syncthreads();
    #pragma unroll
    for (int k = 0; k < 32; k += 8)
        bc[(long)b * SS * DD + (long)(s0 + ty + k) * DD + d0 + tx] = t[tx][ty + k];
}

__global__ void h_copy(const float* __restrict__ in, __half* __restrict__ out, long n) {
    long idx = (long)blockIdx.x * 256 + threadIdx.x;
    if (idx < n) out[idx] = __float2half(in[idx]);
}

__global__ void __launch_bounds__(256) bcast_k(float* xt) {
    __shared__ float a[SS];
    float res[32], nv[32];
    float* g = xt + (long)blockIdx.x * SS;
    int tid = threadIdx.x;
    #pragma unroll
    for (int j = 0; j < 32; j++) { a[tid + 256 * j] = g[tid + 256 * j]; res[j] = 0.0f; }
    __syncthreads();
    for (int s = 1; s < SS; s <<= 1) {
        #pragma unroll
        for (int j = 0; j < 32; j++) {
            int i = tid + 256 * j;
            nv[j] = a[i] + 0.5f * (a[(i - s) & (SS - 1)] + a[(i + s) & (SS - 1)]);
        }
        __syncthreads();
        #pragma unroll
        for (int j = 0; j < 32; j++) { int i = tid + 256 * j; a[i] = nv[j]; res[j] += nv[j]; }
        __syncthreads();
    }
    const float inv = 1.0f / 14.0f;
    #pragma unroll
    for (int j = 0; j < 32; j++) g[tid + 256 * j] = res[j] * inv;
}

__global__ void wc_reorder(const float* __restrict__ Wc, __half* __restrict__ Wc2h) {
    long idx = (long)blockIdx.x * 256 + threadIdx.x;
    int o = (int)(idx >> 12);
    int rem = (int)(idx & 4095);
    int k = rem >> 10;
    int d = rem & 1023;
    Wc2h[idx] = __float2half(Wc[(long)o * 4096 + d * 4 + k]);
}

__global__ void build_gth(const float* __restrict__ gm, __half* __restrict__ gth) {
    long idx = (long)blockIdx.x * 256 + threadIdx.x;
    int b = (int)(idx >> 17);
    int rem = (int)(idx & 131071);
    int row = rem >> 10;
    int d = rem & 1023;
    gth[(long)b * 256 * 1024 + (long)(128 + row) * 1024 + d] = __float2half(gm[(long)row * 1024 + d]);
}

__device__ __forceinline__ float blk_max(float v, float* red) {
    int tid = threadIdx.x;
    #pragma unroll
    for (int o = 16; o; o >>= 1) v = fmaxf(v, __shfl_xor_sync(0xffffffffu, v, o));
    if ((tid & 31) == 0) red[tid >> 5] = v;
    __syncthreads();
    float m = red[0];
    #pragma unroll
    for (int i = 1; i < 8; i++) m = fmaxf(m, red[i]);
    return m;
}
__device__ __forceinline__ float blk_sum(float v, float* red) {
    int tid = threadIdx.x;
    #pragma unroll
    for (int o = 16; o; o >>= 1) v += __shfl_xor_sync(0xffffffffu, v, o);
    if ((tid & 31) == 0) red[tid >> 5] = v;
    __syncthreads();
    float s = 0.f;
    #pragma unroll
    for (int i = 0; i < 8; i++) s += red[i];
    return s;
}

__global__ void softmax256(const float* __restrict__ L, __half* __restrict__ Lh) {
    __shared__ float red[8];
    const float* r = L + (long)blockIdx.x * 256;
    int tid = threadIdx.x;
    float v = r[tid];
    float m = blk_max(v, red);
    __syncthreads();
    float e = expf(v - m);
    float s = blk_sum(e, red);
    Lh[(long)blockIdx.x * 256 + tid] = __float2half(e / s);
}

__global__ void softmax_causal2(const __half* __restrict__ Ddh, const __half* __restrict__ Doh,
                                __half* __restrict__ Ph) {
    __shared__ float red[8];
    int q = blockIdx.x, w = blockIdx.y;
    int b = w / 7, n = w % 7;
    __half* out = Ph + ((long)w * WLEN + q) * WLEN;
    int rb = ((q >> 7) + 1) << 7;
    int tid = threadIdx.x;
    float vA[4], vB[4];
    int cA = 0, cB = 0;
    float m = -1e30f;
    const __half hz = __float2half(0.0f);

    if (q < 1024) {
        const __half* src = Ddh + (((long)(b * 8 + n)) * 1024 + q) * 1024;
        int len = q + 1;
        for (int i = tid; i < len; i += 256) { vA[cA] = __half2float(src[i]); m = fmaxf(m, vA[cA]); cA++; }
        m = blk_max(m, red);
        __syncthreads();
        float s = 0.f;
        #pragma unroll
        for (int j = 0; j < 4; j++) if (j < cA) { vA[j] = expf(vA[j] - m); s += vA[j]; }
        s = blk_sum(s, red);
        float inv = 1.0f / s;
        cA = 0;
        for (int i = tid; i < len; i += 256) out[i] = __float2half(vA[cA++] * inv);
        for (int i = len + tid; i < rb; i += 256) out[i] = hz;
    } else {
        int q2 = q - 1024;
        const __half* srcA = Doh + (((long)(b * 7 + n)) * 1024 + q2) * 1024;
        const __half* srcB = Ddh + (((long)(b * 8 + n + 1)) * 1024 + q2) * 1024;
        int lenB = q2 + 1;
        for (int i = tid; i < 1024; i += 256) { vA[cA] = __half2float(srcA[i]); m = fmaxf(m, vA[cA]); cA++; }
        for (int i = tid; i < lenB; i += 256) { vB[cB] = __half2float(srcB[i]); m = fmaxf(m, vB[cB]); cB++; }
        m = blk_max(m, red);
        __syncthreads();
        float s = 0.f;
        #pragma unroll
        for (int j = 0; j < 4; j++) if (j < cA) { vA[j] = expf(vA[j] - m); s += vA[j]; }
        #pragma unroll
        for (int j = 0; j < 4; j++) if (j < cB) { vB[j] = expf(vB[j] - m); s += vB[j]; }
        s = blk_sum(s, red);
        float inv = 1.0f / s;
        cA = 0; cB = 0;
        for (int i = tid; i < 1024; i += 256) out[i] = __float2half(vA[cA++] * inv);
        for (int i = tid; i < lenB; i += 256) out[1024 + i] = __float2half(vB[cB++] * inv);
        for (int i = 1024 + lenB + tid; i < rb; i += 256) out[i] = hz;
    }
}

__global__ void combine_local(const __half* __restrict__ Oscrh, __half* __restrict__ localh) {
    long idx = (long)blockIdx.x * 256 + threadIdx.x;
    int d = (int)(idx & 1023);
    long pd = idx >> 10;
    int p = (int)(pd & (SS - 1));
    int b = (int)(pd >> 13);
    int nhi = p >> 10;
    int n1 = min(nhi, NWIN - 1);
    int n0 = max(nhi - 1, 0);
    float acc = 0.f, wsum = 0.f;
    for (int n = n0; n <= n1; n++) {
        int q = p - (n << 10);
        float tri = 0.5f + q * (1.0f / 2047.0f);
        acc  += __half2float(Oscrh[(((long)(b * NWIN + n)) * WLEN + q) * DD + d]) * tri;
        wsum += tri;
    }
    localh[idx] = __float2half(acc / (wsum + 1e-6f));
}

extern "C" void kernel_launch(void* const* d_in, const int* in_sizes, int n_in,
                              void* d_out, int out_size) {
    const float* x  = (const float*)d_in[0];
    const float* gm = (const float*)d_in[1];
    const float* Wc = (const float*)d_in[2];
    const float* bc = (const float*)d_in[3];
    const float* Wm = (const float*)d_in[4];
    const float* bm = (const float*)d_in[5];
    const float* Wo = (const float*)d_in[6];
    const float* bo = (const float*)d_in[7];
    float* out = (float*)d_out;

    __half *xh, *Wc2h, *gth, *lg2h, *Ph, *localh, *globh, *mixedh, *Wmh, *Woh, *Ddh, *Doh, *Oscrh;
    float *lg2, *xt, *bcastf;
    cudaGetSymbolAddress((void**)&xh,     g_xh);
    cudaGetSymbolAddress((void**)&Wc2h,   g_Wc2h);
    cudaGetSymbolAddress((void**)&gth,    g_gth);
    cudaGetSymbolAddress((void**)&lg2h,   g_lg2h);
    cudaGetSymbolAddress((void**)&Ph,     g_Ph);
    cudaGetSymbolAddress((void**)&localh, g_localh);
    cudaGetSymbolAddress((void**)&globh,  g_globh);
    cudaGetSymbolAddress((void**)&mixedh, g_mixedh);
    cudaGetSymbolAddress((void**)&Wmh,    g_Wmh);
    cudaGetSymbolAddress((void**)&Woh,    g_Woh);
    cudaGetSymbolAddress((void**)&Ddh,    g_Ddh);
    cudaGetSymbolAddress((void**)&Doh,    g_Doh);
    cudaGetSymbolAddress((void**)&Oscrh,  g_Oscrh);
    cudaGetSymbolAddress((void**)&lg2,    g_lg2);
    cudaGetSymbolAddress((void**)&xt,     g_xt);
    cudaGetSymbolAddress((void**)&bcastf, g_bcast);

    cudaFuncSetAttribute(gemm_h<1>, cudaFuncAttributeMaxDynamicSharedMemorySize, SMEM_TB1);
    cudaFuncSetAttribute(gemm_h<0>, cudaFuncAttributeMaxDynamicSharedMemorySize, SMEM_TB0);

    static cudaStream_t s2 = nullptr;
    static cudaEvent_t ev1 = nullptr, ev2 = nullptr;
    if (!s2) {
        cudaStreamCreateWithFlags(&s2, cudaStreamNonBlocking);
        cudaEventCreateWithFlags(&ev1, cudaEventDisableTiming);
        cudaEventCreateWithFlags(&ev2, cudaEventDisableTiming);
    }

    const float isq = 1.0f / 32.0f;
    const long SD = (long)SS * DD;

    prep_x<<<dim3(32, 256, 2), dim3(32, 8)>>>(x, xh, xt);
    cudaEventRecord(ev1, 0);
    cudaStreamWaitEvent(s2, ev1, 0);

    // ---------- branch B (s2): memory-bound work + global path ----------
    wc_reorder<<<16384, 256, 0, s2>>>(Wc, Wc2h);
    build_gth<<<1024, 256, 0, s2>>>(gm, gth);
    h_copy<<<(2 * 1024 * 1024 + 255) / 256, 256, 0, s2>>>(Wm, Wmh, 2L * 1024 * 1024);
    h_copy<<<(1024 * 1024 + 255) / 256, 256, 0, s2>>>(Wo, Woh, 1024L * 1024);
    bcast_k<<<BB * DD, 256, 0, s2>>>(xt);
    transpose_back<<<dim3(256, 32, 2), dim3(32, 8), 0, s2>>>(xt, bcastf);
    {   // comp: gth rows 0..127 = xh_view(128x4096) @ Wc2h^T + bc
        GP p{}; p.A = xh; p.B = Wc2h; p.Ch = gth; p.bias = bc;
        p.lda = 4096; p.ldb = 4096; p.ldc = 1024;
        p.sA = SD; p.sC = 256L * 1024;
        p.K = 4096; p.alpha = 1.0f;
        gemm_h<1><<<dim3(8, 1, 2), 128, SMEM_TB1, s2>>>(p);
    }
    {   // logits = xh @ gth^T / 32
        GP p{}; p.A = xh; p.B = gth; p.Cf = lg2;
        p.lda = 1024; p.ldb = 1024; p.ldc = 256;
        p.sA = SD; p.sB = 256L * 1024; p.sC = (long)SS * 256;
        p.K = 1024; p.alpha = isq;
        gemm_h<1><<<dim3(2, 64, 2), 128, SMEM_TB1, s2>>>(p);
    }
    softmax256<<<BB * SS, 256, 0, s2>>>(lg2, lg2h);
    {   // glob = attn @ gt (half out)
        GP p{}; p.A = lg2h; p.B = gth; p.Ch = globh;
        p.lda = 256; p.ldb = 1024; p.ldc = 1024;
        p.sA = (long)SS * 256; p.sB = 256L * 1024; p.sC = SD;
        p.K = 256; p.alpha = 1.0f;
        gemm_h<0><<<dim3(8, 64, 2), 128, SMEM_TB0, s2>>>(p);
    }
    cudaEventRecord(ev2, s2);

    // ---------- branch A (default stream): window path ----------
    {   // combined unique score blocks
        GP p{}; p.A = xh; p.B = xh; p.Ch = Ddh; p.Ch2 = Doh;
        p.lda = 1024; p.ldb = 1024; p.ldc = 1024;
        p.sC = 1024L * 1024;
        p.K = 1024; p.alpha = isq;
        p.mode = 4;
        gemm_h<1><<<dim3(8, 8, BB * 8 + BB * 7), 128, SMEM_TB1>>>(p);
    }
    softmax_causal2<<<dim3(WLEN, NBW), 256>>>(Ddh, Doh, Ph);
    {   // out_w = P @ w
        GP p{}; p.A = Ph; p.B = xh; p.Ch = Oscrh;
        p.lda = WLEN; p.ldb = 1024; p.ldc = 1024;
        p.sA = (long)WLEN * WLEN; p.sC = (long)WLEN * DD;
        p.K = WLEN; p.alpha = 1.0f;
        p.winB = 1; p.klimit = 1;
        gemm_h<0><<<dim3(8, 16, NBW), 128, SMEM_TB0>>>(p);
    }
    combine_local<<<65536, 256>>>(Oscrh, localh);

    // ---------- join ----------
    cudaStreamWaitEvent(0, ev2, 0);

    {   // mixed = sigmoid([local|glob]@Wm^T + bm) mix + bcast  (fused epilogue)
        GP p{}; p.A = localh; p.A2 = globh; p.B = Wmh; p.Ch = mixedh;
        p.bias = bm;
        p.mixLoc = localh; p.mixGlob = globh; p.mixBcast = bcastf;
        p.lda = 1024; p.ldb = 2048; p.ldc = 1024;
        p.K = 2048; p.kSplit = 1024; p.alpha = 1.0f;
        p.mixEpi = 1;
        gemm_h<1><<<dim3(8, 128, 1), 128, SMEM_TB1>>>(p);
    }
    {   // out = mixed @ Wo^T + bo
        GP p{}; p.A = mixedh; p.B = Woh; p.Cf = out; p.bias = bo;
        p.lda = 1024; p.ldb = 1024; p.ldc = 1024;
        p.K = 1024; p.alpha = 1.0f;
        gemm_h<1><<<dim3(8, 128, 1), 128, SMEM_TB1>>>(p);
    }
}

// round 15
// speedup vs baseline: 1.0345x; 1.0345x over previous
#include <cuda_runtime.h>
#include <cuda_fp16.h>
#include <mma.h>
#include <math.h>
#include <stdint.h>

using namespace nvcuda;

#define BB   2
#define SS   8192
#define DD   1024
#define NWIN 7
#define NBW  14
#define WLEN 2048
#define GG   128

// ---------------- static scratch ----------------
__device__ __half g_xh    [(size_t)BB * SS * DD];
__device__ __half g_Wc2h  [(size_t)DD * 4096];
__device__ __half g_gth   [(size_t)BB * 256 * DD];
__device__ __half g_lg2h  [(size_t)BB * SS * 256];
__device__ __half g_Ph    [(size_t)NBW * WLEN * WLEN];
__device__ __half g_localh[(size_t)BB * SS * DD];
__device__ __half g_globh [(size_t)BB * SS * DD];
__device__ __half g_mixedh[(size_t)BB * SS * DD];
__device__ __half g_Wmh   [(size_t)DD * 2 * DD];
__device__ __half g_Woh   [(size_t)DD * DD];
__device__ __half g_Ddh   [(size_t)BB * 8 * 1024 * 1024];
__device__ __half g_Doh   [(size_t)BB * 7 * 1024 * 1024];
__device__ __half g_Oscrh [(size_t)NBW * WLEN * DD];
__device__ float  g_lg2   [(size_t)BB * SS * 256];
__device__ float  g_xt    [(size_t)BB * DD * SS];
__device__ float  g_bcast [(size_t)BB * SS * DD];

struct GP {
    const __half* A;
    const __half* A2;
    const __half* B;
    float*  Cf;
    __half* Ch;
    __half* Ch2;          // mode-4 off-diag target
    const float* bias;    // per-column bias
    const __half* mixLoc;     // MIX epilogue inputs
    const __half* mixGlob;
    const float*  mixBcast;
    int lda, ldb, ldc;
    long sA, sB, sC;
    int K, kSplit;
    float alpha;
    int mode;             // 0 normal, 4 combined scores
    int winB;
    int causal, klimit;
};

__device__ __forceinline__ long window_off(int z) {
    return (long)(z / NWIN) * ((long)SS * DD) + (long)(z % NWIN) * (1024L * DD);
}

__device__ __forceinline__ void cp16(void* smem, const void* g) {
    uint32_t s = (uint32_t)__cvta_generic_to_shared(smem);
    asm volatile("cp.async.ca.shared.global [%0], [%1], 16;\n" :: "r"(s), "l"(g));
}
__device__ __forceinline__ void cp_commit() { asm volatile("cp.async.commit_group;\n"); }
template<int N> __device__ __forceinline__ void cp_wait() { asm volatile("cp.async.wait_group %0;\n" :: "n"(N)); }

// TB=1: C = A*B^T ; TB=0: C = A*B. fp16 operands, fp32 accumulate.
// MIX=1: epilogue computes sigmoid gate mix (Wm GEMM only).
template<int TB, int MIX>
__global__ void __launch_bounds__(128) gemm_h(GP p) {
    constexpr int BM = 128, BN = 128, BK = 32, ST = 4;
    constexpr int ALD = 40;
    constexpr int BLD = TB ? 40 : 136;
    constexpr int BROWS = TB ? 128 : 32;
    constexpr int ASTG = BM * ALD;
    constexpr int BSTG = BROWS * BLD;

    int i0 = blockIdx.y * BM;
    int j0 = blockIdx.x * BN;
    if (p.causal && j0 > i0) return;
    int z = blockIdx.z;
    const __half* A;
    const __half* Bm;
    __half* ChBase = p.Ch;
    int zc = z;
    if (p.mode == 4) {
        if (z < BB * 8) {
            if (j0 > i0) return;
            long o = (long)(z >> 3) * ((long)SS * DD) + (long)(z & 7) * (1024L * DD);
            A = p.A + o; Bm = p.B + o;
        } else {
            int zz = z - BB * 8;
            int b = zz / 7, n = zz % 7;
            A  = p.A + (long)b * ((long)SS * DD) + (long)(n + 1) * (1024L * DD);
            Bm = p.B + (long)b * ((long)SS * DD) + (long)n * (1024L * DD);
            ChBase = p.Ch2; zc = zz;
        }
    }
    else { A = p.A + z * p.sA; Bm = p.B + (p.winB ? window_off(z) : z * p.sB); }
    float*  Cf = p.Cf ? p.Cf + z * p.sC : nullptr;
    __half* Ch = ChBase ? ChBase + zc * p.sC : nullptr;
    int K  = p.klimit ? min(p.K, i0 + BM) : p.K;
    int KT = K / BK;

    extern __shared__ __half smem_h[];
    __half* Asm = smem_h;
    __half* Bsm = smem_h + ST * ASTG;

    int tid = threadIdx.x;
    int ar = tid >> 2, ac = (tid & 3) << 3;
    int br, bcd;
    if (TB) { br = tid >> 2;  bcd = (tid & 3) << 3;  }
    else    { br = tid >> 4;  bcd = (tid & 15) << 3; }

    auto load_tile = [&](int kt, int sl) {
        long acol = (long)kt * BK;
        const __half* Ag;
        if (p.A2 && acol >= p.kSplit)
            Ag = p.A2 + (long)(i0 + ar) * p.lda + (acol - p.kSplit) + ac;
        else
            Ag = A + (long)(i0 + ar) * p.lda + acol + ac;
        __half* As = Asm + sl * ASTG;
        #pragma unroll
        for (int q = 0; q < 4; q++)
            cp16(&As[(ar + 32 * q) * ALD + ac], Ag + (long)(32 * q) * p.lda);
        __half* Bs = Bsm + sl * BSTG;
        if (TB) {
            const __half* Bg = Bm + (long)(j0 + br) * p.ldb + acol + bcd;
            #pragma unroll
            for (int q = 0; q < 4; q++)
                cp16(&Bs[(br + 32 * q) * BLD + bcd], Bg + (long)(32 * q) * p.ldb);
        } else {
            const __half* Bg = Bm + (acol + br) * (long)p.ldb + j0 + bcd;
            #pragma unroll
            for (int q = 0; q < 4; q++)
                cp16(&Bs[(br + 8 * q) * BLD + bcd], Bg + (long)(8 * q) * p.ldb);
        }
    };

    #pragma unroll
    for (int s = 0; s < ST - 1; s++) {
        if (s < KT) load_tile(s, s);
        cp_commit();
    }

    int wid = tid >> 5;
    int lane = tid & 31;
    int wr  = (wid & 1) * 64;
    int wc  = (wid >> 1) * 64;

    wmma::fragment<wmma::accumulator, 16, 16, 16, float> acc[4][4];
    #pragma unroll
    for (int i = 0; i < 4; i++)
        #pragma unroll
        for (int j = 0; j < 4; j++) wmma::fill_fragment(acc[i][j], 0.0f);

    for (int kt = 0; kt < KT; kt++) {
        cp_wait<ST - 2>();
        __syncthreads();
        if (kt + ST - 1 < KT) load_tile(kt + ST - 1, (kt + ST - 1) & (ST - 1));
        cp_commit();

        int sl = kt & (ST - 1);
        const __half* As = Asm + sl * ASTG;
        const __half* Bs = Bsm + sl * BSTG;

        #pragma unroll
        for (int ks = 0; ks < 2; ks++) {
            wmma::fragment<wmma::matrix_a, 16, 16, 16, __half, wmma::row_major> af[4];
            #pragma unroll
            for (int i = 0; i < 4; i++)
                wmma::load_matrix_sync(af[i], &As[(wr + i * 16) * ALD + ks * 16], ALD);
            #pragma unroll
            for (int j = 0; j < 4; j++) {
                if (TB) {
                    wmma::fragment<wmma::matrix_b, 16, 16, 16, __half, wmma::col_major> bf;
                    wmma::load_matrix_sync(bf, &Bs[(wc + j * 16) * BLD + ks * 16], BLD);
                    #pragma unroll
                    for (int i = 0; i < 4; i++)
                        wmma::mma_sync(acc[i][j], af[i], bf, acc[i][j]);
                } else {
                    wmma::fragment<wmma::matrix_b, 16, 16, 16, __half, wmma::row_major> bf;
                    wmma::load_matrix_sync(bf, &Bs[(ks * 16) * BLD + wc + j * 16], BLD);
                    #pragma unroll
                    for (int i = 0; i < 4; i++)
                        wmma::mma_sync(acc[i][j], af[i], bf, acc[i][j]);
                }
            }
        }
    }

    // ---- staged epilogue ----
    __syncthreads();
    float* stg = reinterpret_cast<float*>(smem_h) + wid * (64 * 72);
    #pragma unroll
    for (int i = 0; i < 4; i++)
        #pragma unroll
        for (int j = 0; j < 4; j++)
            wmma::store_matrix_sync(&stg[(i * 16) * 72 + j * 16], acc[i][j], 72, wmma::mem_row_major);
    __syncwarp();

    int rbase = i0 + wr;
    int cbase = j0 + wc;
    #pragma unroll
    for (int rr = 0; rr < 64; rr += 8) {
        int r = rr + (lane >> 2);
        int c = (lane & 3) << 4;
        long gro = (long)(rbase + r) * p.ldc + cbase + c;
        #pragma unroll
        for (int q = 0; q < 4; q++) {
            float4 v = *(float4*)&stg[r * 72 + c + q * 4];
            v.x *= p.alpha; v.y *= p.alpha; v.z *= p.alpha; v.w *= p.alpha;
            if (p.bias) {
                float4 b = *(const float4*)&p.bias[cbase + c + q * 4];
                v.x += b.x; v.y += b.y; v.z += b.z; v.w += b.w;
            }
            if constexpr (MIX) {
                float2 l0 = __half22float2(*(const __half2*)&p.mixLoc[gro + q * 4]);
                float2 l1 = __half22float2(*(const __half2*)&p.mixLoc[gro + q * 4 + 2]);
                float2 g0 = __half22float2(*(const __half2*)&p.mixGlob[gro + q * 4]);
                float2 g1 = __half22float2(*(const __half2*)&p.mixGlob[gro + q * 4 + 2]);
                float4 bc = *(const float4*)&p.mixBcast[gro + q * 4];
                float s0 = 1.0f / (1.0f + __expf(-v.x));
                float s1 = 1.0f / (1.0f + __expf(-v.y));
                float s2v = 1.0f / (1.0f + __expf(-v.z));
                float s3 = 1.0f / (1.0f + __expf(-v.w));
                v.x = s0 * l0.x + (1.0f - s0) * g0.x + bc.x;
                v.y = s1 * l0.y + (1.0f - s1) * g0.y + bc.y;
                v.z = s2v * l1.x + (1.0f - s2v) * g1.x + bc.z;
                v.w = s3 * l1.y + (1.0f - s3) * g1.y + bc.w;
            }
            if (Cf) *(float4*)&Cf[gro + q * 4] = v;
            if (Ch) {
                *(__half2*)&Ch[gro + q * 4]     = __floats2half2_rn(v.x, v.y);
                *(__half2*)&Ch[gro + q * 4 + 2] = __floats2half2_rn(v.z, v.w);
            }
        }
    }
}

#define SMEM_TB1 ((4 * (128 * 40) + 4 * (128 * 40)) * 2)
#define SMEM_TB0 ((4 * (128 * 40) + 4 * (32 * 136)) * 2)

// ---------------- elementwise ----------------
__global__ void prep_x(const float* __restrict__ x, __half* __restrict__ xh, float* __restrict__ xt) {
    __shared__ float t[32][33];
    int b = blockIdx.z;
    long bo = (long)b * SS * DD;
    int s0 = blockIdx.y * 32, d0 = blockIdx.x * 32;
    int tx = threadIdx.x, ty = threadIdx.y;
    #pragma unroll
    for (int k = 0; k < 32; k += 8) {
        long gi = bo + (long)(s0 + ty + k) * DD + d0 + tx;
        float v = x[gi];
        t[ty + k][tx] = v;
        xh[gi] = __float2half(v);
    }
    __syncthreads();
    #pragma unroll
    for (int k = 0; k < 32; k += 8)
        xt[(long)b * DD * SS + (long)(d0 + ty + k) * SS + s0 + tx] = t[tx][ty + k];
}

// transpose (b, d, s) -> (b, s, d)
__global__ void transpose_back(const float* __restrict__ xt, float* __restrict__ bc) {
    __shared__ float t[32][33];
    int b = blockIdx.z;
    int s0 = blockIdx.x * 32, d0 = blockIdx.y * 32;
    int tx = threadIdx.x, ty = threadIdx.y;
    #pragma unroll
    for (int k = 0; k < 32; k += 8)
        t[ty + k][tx] = xt[(long)b * DD * SS + (long)(d0 + ty + k) * SS + s0 + tx];
    __syncthreads();
    #pragma unroll
    for (int k = 0; k < 32; k += 8)
        bc[(long)b * SS * DD + (long)(s0 + ty + k) * DD + d0 + tx] = t[tx][ty + k];
}

__global__ void h_copy(const float* __restrict__ in, __half* __restrict__ out, long n) {
    long idx = (long)blockIdx.x * 256 + threadIdx.x;
    if (idx < n) out[idx] = __float2half(in[idx]);
}

__global__ void __launch_bounds__(256) bcast_k(float* xt) {
    __shared__ float a[SS];
    float res[32], nv[32];
    float* g = xt + (long)blockIdx.x * SS;
    int tid = threadIdx.x;
    #pragma unroll
    for (int j = 0; j < 32; j++) { a[tid + 256 * j] = g[tid + 256 * j]; res[j] = 0.0f; }
    __syncthreads();
    for (int s = 1; s < SS; s <<= 1) {
        #pragma unroll
        for (int j = 0; j < 32; j++) {
            int i = tid + 256 * j;
            nv[j] = a[i] + 0.5f * (a[(i - s) & (SS - 1)] + a[(i + s) & (SS - 1)]);
        }
        __syncthreads();
        #pragma unroll
        for (int j = 0; j < 32; j++) { int i = tid + 256 * j; a[i] = nv[j]; res[j] += nv[j]; }
        __syncthreads();
    }
    const float inv = 1.0f / 14.0f;
    #pragma unroll
    for (int j = 0; j < 32; j++) g[tid + 256 * j] = res[j] * inv;
}

__global__ void wc_reorder(const float* __restrict__ Wc, __half* __restrict__ Wc2h) {
    long idx = (long)blockIdx.x * 256 + threadIdx.x;
    int o = (int)(idx >> 12);
    int rem = (int)(idx & 4095);
    int k = rem >> 10;
    int d = rem & 1023;
    Wc2h[idx] = __float2half(Wc[(long)o * 4096 + d * 4 + k]);
}

__global__ void build_gth(const float* __restrict__ gm, __half* __restrict__ gth) {
    long idx = (long)blockIdx.x * 256 + threadIdx.x;
    int b = (int)(idx >> 17);
    int rem = (int)(idx & 131071);
    int row = rem >> 10;
    int d = rem & 1023;
    gth[(long)b * 256 * 1024 + (long)(128 + row) * 1024 + d] = __float2half(gm[(long)row * 1024 + d]);
}

__device__ __forceinline__ float blk_max(float v, float* red) {
    int tid = threadIdx.x;
    #pragma unroll
    for (int o = 16; o; o >>= 1) v = fmaxf(v, __shfl_xor_sync(0xffffffffu, v, o));
    if ((tid & 31) == 0) red[tid >> 5] = v;
    __syncthreads();
    float m = red[0];
    #pragma unroll
    for (int i = 1; i < 8; i++) m = fmaxf(m, red[i]);
    return m;
}
__device__ __forceinline__ float blk_sum(float v, float* red) {
    int tid = threadIdx.x;
    #pragma unroll
    for (int o = 16; o; o >>= 1) v += __shfl_xor_sync(0xffffffffu, v, o);
    if ((tid & 31) == 0) red[tid >> 5] = v;
    __syncthreads();
    float s = 0.f;
    #pragma unroll
    for (int i = 0; i < 8; i++) s += red[i];
    return s;
}

__global__ void softmax256(const float* __restrict__ L, __half* __restrict__ Lh) {
    __shared__ float red[8];
    const float* r = L + (long)blockIdx.x * 256;
    int tid = threadIdx.x;
    float v = r[tid];
    float m = blk_max(v, red);
    __syncthreads();
    float e = expf(v - m);
    float s = blk_sum(e, red);
    Lh[(long)blockIdx.x * 256 + tid] = __float2half(e / s);
}

__global__ void softmax_causal2(const __half* __restrict__ Ddh, const __half* __restrict__ Doh,
                                __half* __restrict__ Ph) {
    __shared__ float red[8];
    int q = blockIdx.x, w = blockIdx.y;
    int b = w / 7, n = w % 7;
    __half* out = Ph + ((long)w * WLEN + q) * WLEN;
    int rb = ((q >> 7) + 1) << 7;
    int tid = threadIdx.x;
    float vA[4], vB[4];
    int cA = 0, cB = 0;
    float m = -1e30f;
    const __half hz = __float2half(0.0f);

    if (q < 1024) {
        const __half* src = Ddh + (((long)(b * 8 + n)) * 1024 + q) * 1024;
        int len = q + 1;
        for (int i = tid; i < len; i += 256) { vA[cA] = __half2float(src[i]); m = fmaxf(m, vA[cA]); cA++; }
        m = blk_max(m, red);
        __syncthreads();
        float s = 0.f;
        #pragma unroll
        for (int j = 0; j < 4; j++) if (j < cA) { vA[j] = expf(vA[j] - m); s += vA[j]; }
        s = blk_sum(s, red);
        float inv = 1.0f / s;
        cA = 0;
        for (int i = tid; i < len; i += 256) out[i] = __float2half(vA[cA++] * inv);
        for (int i = len + tid; i < rb; i += 256) out[i] = hz;
    } else {
        int q2 = q - 1024;
        const __half* srcA = Doh + (((long)(b * 7 + n)) * 1024 + q2) * 1024;
        const __half* srcB = Ddh + (((long)(b * 8 + n + 1)) * 1024 + q2) * 1024;
        int lenB = q2 + 1;
        for (int i = tid; i < 1024; i += 256) { vA[cA] = __half2float(srcA[i]); m = fmaxf(m, vA[cA]); cA++; }
        for (int i = tid; i < lenB; i += 256) { vB[cB] = __half2float(srcB[i]); m = fmaxf(m, vB[cB]); cB++; }
        m = blk_max(m, red);
        __syncthreads();
        float s = 0.f;
        #pragma unroll
        for (int j = 0; j < 4; j++) if (j < cA) { vA[j] = expf(vA[j] - m); s += vA[j]; }
        #pragma unroll
        for (int j = 0; j < 4; j++) if (j < cB) { vB[j] = expf(vB[j] - m); s += vB[j]; }
        s = blk_sum(s, red);
        float inv = 1.0f / s;
        cA = 0; cB = 0;
        for (int i = tid; i < 1024; i += 256) out[i] = __float2half(vA[cA++] * inv);
        for (int i = tid; i < lenB; i += 256) out[1024 + i] = __float2half(vB[cB++] * inv);
        for (int i = 1024 + lenB + tid; i < rb; i += 256) out[i] = hz;
    }
}

__global__ void combine_local(const __half* __restrict__ Oscrh, __half* __restrict__ localh) {
    long idx = (long)blockIdx.x * 256 + threadIdx.x;
    int d = (int)(idx & 1023);
    long pd = idx >> 10;
    int p = (int)(pd & (SS - 1));
    int b = (int)(pd >> 13);
    int nhi = p >> 10;
    int n1 = min(nhi, NWIN - 1);
    int n0 = max(nhi - 1, 0);
    float acc = 0.f, wsum = 0.f;
    for (int n = n0; n <= n1; n++) {
        int q = p - (n << 10);
        float tri = 0.5f + q * (1.0f / 2047.0f);
        acc  += __half2float(Oscrh[(((long)(b * NWIN + n)) * WLEN + q) * DD + d]) * tri;
        wsum += tri;
    }
    localh[idx] = __float2half(acc / (wsum + 1e-6f));
}

extern "C" void kernel_launch(void* const* d_in, const int* in_sizes, int n_in,
                              void* d_out, int out_size) {
    const float* x  = (const float*)d_in[0];
    const float* gm = (const float*)d_in[1];
    const float* Wc = (const float*)d_in[2];
    const float* bc = (const float*)d_in[3];
    const float* Wm = (const float*)d_in[4];
    const float* bm = (const float*)d_in[5];
    const float* Wo = (const float*)d_in[6];
    const float* bo = (const float*)d_in[7];
    float* out = (float*)d_out;

    __half *xh, *Wc2h, *gth, *lg2h, *Ph, *localh, *globh, *mixedh, *Wmh, *Woh, *Ddh, *Doh, *Oscrh;
    float *lg2, *xt, *bcastf;
    cudaGetSymbolAddress((void**)&xh,     g_xh);
    cudaGetSymbolAddress((void**)&Wc2h,   g_Wc2h);
    cudaGetSymbolAddress((void**)&gth,    g_gth);
    cudaGetSymbolAddress((void**)&lg2h,   g_lg2h);
    cudaGetSymbolAddress((void**)&Ph,     g_Ph);
    cudaGetSymbolAddress((void**)&localh, g_localh);
    cudaGetSymbolAddress((void**)&globh,  g_globh);
    cudaGetSymbolAddress((void**)&mixedh, g_mixedh);
    cudaGetSymbolAddress((void**)&Wmh,    g_Wmh);
    cudaGetSymbolAddress((void**)&Woh,    g_Woh);
    cudaGetSymbolAddress((void**)&Ddh,    g_Ddh);
    cudaGetSymbolAddress((void**)&Doh,    g_Doh);
    cudaGetSymbolAddress((void**)&Oscrh,  g_Oscrh);
    cudaGetSymbolAddress((void**)&lg2,    g_lg2);
    cudaGetSymbolAddress((void**)&xt,     g_xt);
    cudaGetSymbolAddress((void**)&bcastf, g_bcast);

    cudaFuncSetAttribute((const void*)gemm_h<1,0>, cudaFuncAttributeMaxDynamicSharedMemorySize, SMEM_TB1);
    cudaFuncSetAttribute((const void*)gemm_h<1,1>, cudaFuncAttributeMaxDynamicSharedMemorySize, SMEM_TB1);
    cudaFuncSetAttribute((const void*)gemm_h<0,0>, cudaFuncAttributeMaxDynamicSharedMemorySize, SMEM_TB0);

    static cudaStream_t s2 = nullptr;
    static cudaEvent_t ev1 = nullptr, ev2 = nullptr;
    if (!s2) {
        cudaStreamCreateWithFlags(&s2, cudaStreamNonBlocking);
        cudaEventCreateWithFlags(&ev1, cudaEventDisableTiming);
        cudaEventCreateWithFlags(&ev2, cudaEventDisableTiming);
    }

    const float isq = 1.0f / 32.0f;
    const long SD = (long)SS * DD;

    prep_x<<<dim3(32, 256, 2), dim3(32, 8)>>>(x, xh, xt);
    cudaEventRecord(ev1, 0);
    cudaStreamWaitEvent(s2, ev1, 0);

    // ---------- branch B (s2): memory-bound work + global path ----------
    wc_reorder<<<16384, 256, 0, s2>>>(Wc, Wc2h);
    build_gth<<<1024, 256, 0, s2>>>(gm, gth);
    h_copy<<<(2 * 1024 * 1024 + 255) / 256, 256, 0, s2>>>(Wm, Wmh, 2L * 1024 * 1024);
    h_copy<<<(1024 * 1024 + 255) / 256, 256, 0, s2>>>(Wo, Woh, 1024L * 1024);
    bcast_k<<<BB * DD, 256, 0, s2>>>(xt);
    transpose_back<<<dim3(256, 32, 2), dim3(32, 8), 0, s2>>>(xt, bcastf);
    {   // comp: gth rows 0..127 = xh_view(128x4096) @ Wc2h^T + bc
        GP p{}; p.A = xh; p.B = Wc2h; p.Ch = gth; p.bias = bc;
        p.lda = 4096; p.ldb = 4096; p.ldc = 1024;
        p.sA = SD; p.sC = 256L * 1024;
        p.K = 4096; p.alpha = 1.0f;
        gemm_h<1,0><<<dim3(8, 1, 2), 128, SMEM_TB1, s2>>>(p);
    }
    {   // logits = xh @ gth^T / 32
        GP p{}; p.A = xh; p.B = gth; p.Cf = lg2;
        p.lda = 1024; p.ldb = 1024; p.ldc = 256;
        p.sA = SD; p.sB = 256L * 1024; p.sC = (long)SS * 256;
        p.K = 1024; p.alpha = isq;
        gemm_h<1,0><<<dim3(2, 64, 2), 128, SMEM_TB1, s2>>>(p);
    }
    softmax256<<<BB * SS, 256, 0, s2>>>(lg2, lg2h);
    {   // glob = attn @ gt (half out)
        GP p{}; p.A = lg2h; p.B = gth; p.Ch = globh;
        p.lda = 256; p.ldb = 1024; p.ldc = 1024;
        p.sA = (long)SS * 256; p.sB = 256L * 1024; p.sC = SD;
        p.K = 256; p.alpha = 1.0f;
        gemm_h<0,0><<<dim3(8, 64, 2), 128, SMEM_TB0, s2>>>(p);
    }
    cudaEventRecord(ev2, s2);

    // ---------- branch A (default stream): window path ----------
    {   // combined unique score blocks
        GP p{}; p.A = xh; p.B = xh; p.Ch = Ddh; p.Ch2 = Doh;
        p.lda = 1024; p.ldb = 1024; p.ldc = 1024;
        p.sC = 1024L * 1024;
        p.K = 1024; p.alpha = isq;
        p.mode = 4;
        gemm_h<1,0><<<dim3(8, 8, BB * 8 + BB * 7), 128, SMEM_TB1>>>(p);
    }
    softmax_causal2<<<dim3(WLEN, NBW), 256>>>(Ddh, Doh, Ph);
    {   // out_w = P @ w
        GP p{}; p.A = Ph; p.B = xh; p.Ch = Oscrh;
        p.lda = WLEN; p.ldb = 1024; p.ldc = 1024;
        p.sA = (long)WLEN * WLEN; p.sC = (long)WLEN * DD;
        p.K = WLEN; p.alpha = 1.0f;
        p.winB = 1; p.klimit = 1;
        gemm_h<0,0><<<dim3(8, 16, NBW), 128, SMEM_TB0>>>(p);
    }
    combine_local<<<65536, 256>>>(Oscrh, localh);

    // ---------- join ----------
    cudaStreamWaitEvent(0, ev2, 0);

    {   // mixed = sigmoid([local|glob]@Wm^T + bm) gate mix + bcast  (MIX epilogue)
        GP p{}; p.A = localh; p.A2 = globh; p.B = Wmh; p.Ch = mixedh;
        p.bias = bm;
        p.mixLoc = localh; p.mixGlob = globh; p.mixBcast = bcastf;
        p.lda = 1024; p.ldb = 2048; p.ldc = 1024;
        p.K = 2048; p.kSplit = 1024; p.alpha = 1.0f;
        gemm_h<1,1><<<dim3(8, 128, 1), 128, SMEM_TB1>>>(p);
    }
    {   // out = mixed @ Wo^T + bo
        GP p{}; p.A = mixedh; p.B = Woh; p.Cf = out; p.bias = bo;
        p.lda = 1024; p.ldb = 1024; p.ldc = 1024;
        p.K = 1024; p.alpha = 1.0f;
        gemm_h<1,0><<<dim3(8, 128, 1), 128, SMEM_TB1>>>(p);
    }
}

// round 16
// speedup vs baseline: 1.0698x; 1.0341x over previous
#include <cuda_runtime.h>
#include <cuda_fp16.h>
#include <mma.h>
#include <math.h>
#include <stdint.h>

using namespace nvcuda;

#define BB   2
#define SS   8192
#define DD   1024
#define NWIN 7
#define NBW  14
#define WLEN 2048
#define GG   128

// ---------------- static scratch ----------------
__device__ __half g_xh    [(size_t)BB * SS * DD];
__device__ __half g_Wc2h  [(size_t)DD * 4096];
__device__ __half g_gth   [(size_t)BB * 256 * DD];
__device__ __half g_lg2h  [(size_t)BB * SS * 256];
__device__ __half g_Ph    [(size_t)NBW * WLEN * WLEN];   // P; later reused as mw logits
__device__ __half g_localh[(size_t)BB * SS * DD];
__device__ __half g_globh [(size_t)BB * SS * DD];
__device__ __half g_mixedh[(size_t)BB * SS * DD];
__device__ __half g_Wmh   [(size_t)DD * 2 * DD];
__device__ __half g_Woh   [(size_t)DD * DD];
__device__ __half g_Ddh   [(size_t)BB * 8 * 1024 * 1024];
__device__ __half g_Doh   [(size_t)BB * 7 * 1024 * 1024];
__device__ __half g_Oscrh [(size_t)NBW * WLEN * DD];
__device__ float  g_lg2   [(size_t)BB * SS * 256];
__device__ float  g_xt    [(size_t)BB * DD * SS];

struct GP {
    const __half* A;
    const __half* A2;
    const __half* B;
    float*  Cf;
    __half* Ch;
    __half* Ch2;          // mode-4 off-diag target
    const float* bias;
    int lda, ldb, ldc;
    long sA, sB, sC;
    int K, kSplit;
    float alpha;
    int mode;             // 0 normal, 4 combined scores
    int winB;
    int causal, klimit;
};

__device__ __forceinline__ long window_off(int z) {
    return (long)(z / NWIN) * ((long)SS * DD) + (long)(z % NWIN) * (1024L * DD);
}

__device__ __forceinline__ void cp16(void* smem, const void* g) {
    uint32_t s = (uint32_t)__cvta_generic_to_shared(smem);
    asm volatile("cp.async.ca.shared.global [%0], [%1], 16;\n" :: "r"(s), "l"(g));
}
__device__ __forceinline__ void cp_commit() { asm volatile("cp.async.commit_group;\n"); }
template<int N> __device__ __forceinline__ void cp_wait() { asm volatile("cp.async.wait_group %0;\n" :: "n"(N)); }

// TB=1: C = A*B^T ; TB=0: C = A*B. fp16 operands, fp32 accumulate.
// 4 warps, 64x64 per warp, BK=64, 3-stage cp.async, staged smem epilogue.
template<int TB>
__global__ void __launch_bounds__(128) gemm_h(GP p) {
    constexpr int BM = 128, BN = 128, BK = 64, ST = 3;
    constexpr int ALD = 72;
    constexpr int BLD = TB ? 72 : 136;
    constexpr int BROWS = TB ? 128 : 64;
    constexpr int ASTG = BM * ALD;
    constexpr int BSTG = BROWS * BLD;

    int i0 = blockIdx.y * BM;
    int j0 = blockIdx.x * BN;
    if (p.causal && j0 > i0) return;
    int z = blockIdx.z;
    const __half* A;
    const __half* Bm;
    __half* ChBase = p.Ch;
    int zc = z;
    if (p.mode == 4) {
        if (z < BB * 8) {
            if (j0 > i0) return;
            long o = (long)(z >> 3) * ((long)SS * DD) + (long)(z & 7) * (1024L * DD);
            A = p.A + o; Bm = p.B + o;
        } else {
            int zz = z - BB * 8;
            int b = zz / 7, n = zz % 7;
            A  = p.A + (long)b * ((long)SS * DD) + (long)(n + 1) * (1024L * DD);
            Bm = p.B + (long)b * ((long)SS * DD) + (long)n * (1024L * DD);
            ChBase = p.Ch2; zc = zz;
        }
    }
    else { A = p.A + z * p.sA; Bm = p.B + (p.winB ? window_off(z) : z * p.sB); }
    float*  Cf = p.Cf ? p.Cf + z * p.sC : nullptr;
    __half* Ch = ChBase ? ChBase + zc * p.sC : nullptr;
    int K  = p.klimit ? min(p.K, i0 + BM) : p.K;
    int KT = K / BK;

    extern __shared__ __half smem_h[];
    __half* Asm = smem_h;
    __half* Bsm = smem_h + ST * ASTG;

    int tid = threadIdx.x;
    int ar = tid >> 3, ac = (tid & 7) << 3;   // A: 16 row groups, 8 chunks of 8 halves
    int br, bcd;
    if (TB) { br = tid >> 3;  bcd = (tid & 7) << 3;  }   // 128 rows x 64 halves
    else    { br = tid >> 4;  bcd = (tid & 15) << 3; }   // 64 rows x 128 halves

    auto load_tile = [&](int kt, int sl) {
        long acol = (long)kt * BK;
        const __half* Ag;
        if (p.A2 && acol >= p.kSplit)
            Ag = p.A2 + (long)(i0 + ar) * p.lda + (acol - p.kSplit) + ac;
        else
            Ag = A + (long)(i0 + ar) * p.lda + acol + ac;
        __half* As = Asm + sl * ASTG;
        #pragma unroll
        for (int q = 0; q < 8; q++)
            cp16(&As[(ar + 16 * q) * ALD + ac], Ag + (long)(16 * q) * p.lda);
        __half* Bs = Bsm + sl * BSTG;
        if (TB) {
            const __half* Bg = Bm + (long)(j0 + br) * p.ldb + acol + bcd;
            #pragma unroll
            for (int q = 0; q < 8; q++)
                cp16(&Bs[(br + 16 * q) * BLD + bcd], Bg + (long)(16 * q) * p.ldb);
        } else {
            const __half* Bg = Bm + (acol + br) * (long)p.ldb + j0 + bcd;
            #pragma unroll
            for (int q = 0; q < 8; q++)
                cp16(&Bs[(br + 8 * q) * BLD + bcd], Bg + (long)(8 * q) * p.ldb);
        }
    };

    #pragma unroll
    for (int s = 0; s < ST - 1; s++) {
        if (s < KT) load_tile(s, s);
        cp_commit();
    }

    int wid = tid >> 5;
    int lane = tid & 31;
    int wr  = (wid & 1) * 64;
    int wc  = (wid >> 1) * 64;

    wmma::fragment<wmma::accumulator, 16, 16, 16, float> acc[4][4];
    #pragma unroll
    for (int i = 0; i < 4; i++)
        #pragma unroll
        for (int j = 0; j < 4; j++) wmma::fill_fragment(acc[i][j], 0.0f);

    for (int kt = 0; kt < KT; kt++) {
        cp_wait<ST - 2>();
        __syncthreads();
        if (kt + ST - 1 < KT) load_tile(kt + ST - 1, (kt + ST - 1) % ST);
        cp_commit();

        int sl = kt % ST;
        const __half* As = Asm + sl * ASTG;
        const __half* Bs = Bsm + sl * BSTG;

        #pragma unroll
        for (int ks = 0; ks < 4; ks++) {
            wmma::fragment<wmma::matrix_a, 16, 16, 16, __half, wmma::row_major> af[4];
            #pragma unroll
            for (int i = 0; i < 4; i++)
                wmma::load_matrix_sync(af[i], &As[(wr + i * 16) * ALD + ks * 16], ALD);
            #pragma unroll
            for (int j = 0; j < 4; j++) {
                if (TB) {
                    wmma::fragment<wmma::matrix_b, 16, 16, 16, __half, wmma::col_major> bf;
                    wmma::load_matrix_sync(bf, &Bs[(wc + j * 16) * BLD + ks * 16], BLD);
                    #pragma unroll
                    for (int i = 0; i < 4; i++)
                        wmma::mma_sync(acc[i][j], af[i], bf, acc[i][j]);
                } else {
                    wmma::fragment<wmma::matrix_b, 16, 16, 16, __half, wmma::row_major> bf;
                    wmma::load_matrix_sync(bf, &Bs[(ks * 16) * BLD + wc + j * 16], BLD);
                    #pragma unroll
                    for (int i = 0; i < 4; i++)
                        wmma::mma_sync(acc[i][j], af[i], bf, acc[i][j]);
                }
            }
        }
    }

    // ---- staged epilogue: smem -> coalesced global (float and/or half, + bias) ----
    __syncthreads();
    float* stg = reinterpret_cast<float*>(smem_h) + wid * (64 * 72);
    #pragma unroll
    for (int i = 0; i < 4; i++)
        #pragma unroll
        for (int j = 0; j < 4; j++)
            wmma::store_matrix_sync(&stg[(i * 16) * 72 + j * 16], acc[i][j], 72, wmma::mem_row_major);
    __syncwarp();

    int rbase = i0 + wr;
    int cbase = j0 + wc;
    #pragma unroll
    for (int rr = 0; rr < 64; rr += 8) {
        int r = rr + (lane >> 2);
        int c = (lane & 3) << 4;
        long gro = (long)(rbase + r) * p.ldc + cbase + c;
        #pragma unroll
        for (int q = 0; q < 4; q++) {
            float4 v = *(float4*)&stg[r * 72 + c + q * 4];
            v.x *= p.alpha; v.y *= p.alpha; v.z *= p.alpha; v.w *= p.alpha;
            if (p.bias) {
                float4 b = *(const float4*)&p.bias[cbase + c + q * 4];
                v.x += b.x; v.y += b.y; v.z += b.z; v.w += b.w;
            }
            if (Cf) *(float4*)&Cf[gro + q * 4] = v;
            if (Ch) {
                *(__half2*)&Ch[gro + q * 4]     = __floats2half2_rn(v.x, v.y);
                *(__half2*)&Ch[gro + q * 4 + 2] = __floats2half2_rn(v.z, v.w);
            }
        }
    }
}

#define SMEM_TB1 ((3 * (128 * 72) + 3 * (128 * 72)) * 2)
#define SMEM_TB0 ((3 * (128 * 72) + 3 * (64 * 136)) * 2)

// ---------------- fused elementwise ----------------
__global__ void prep_x(const float* __restrict__ x, __half* __restrict__ xh, float* __restrict__ xt) {
    __shared__ float t[32][33];
    int b = blockIdx.z;
    long bo = (long)b * SS * DD;
    int s0 = blockIdx.y * 32, d0 = blockIdx.x * 32;
    int tx = threadIdx.x, ty = threadIdx.y;
    #pragma unroll
    for (int k = 0; k < 32; k += 8) {
        long gi = bo + (long)(s0 + ty + k) * DD + d0 + tx;
        float v = x[gi];
        t[ty + k][tx] = v;
        xh[gi] = __float2half(v);
    }
    __syncthreads();
    #pragma unroll
    for (int k = 0; k < 32; k += 8)
        xt[(long)b * DD * SS + (long)(d0 + ty + k) * SS + s0 + tx] = t[tx][ty + k];
}

__global__ void transpose_mix(const float* __restrict__ xt, const __half* __restrict__ mwlh,
                              const float* __restrict__ bm, const __half* __restrict__ localh,
                              const __half* __restrict__ globh, __half* __restrict__ mixedh) {
    __shared__ float t[32][33];
    int b = blockIdx.z;
    int s0 = blockIdx.x * 32, d0 = blockIdx.y * 32;
    int tx = threadIdx.x, ty = threadIdx.y;
    #pragma unroll
    for (int k = 0; k < 32; k += 8)
        t[ty + k][tx] = xt[(long)b * DD * SS + (long)(d0 + ty + k) * SS + s0 + tx];
    __syncthreads();
    #pragma unroll
    for (int k = 0; k < 32; k += 8) {
        long idx = (long)b * SS * DD + (long)(s0 + ty + k) * DD + d0 + tx;
        float bcv = t[tx][ty + k];
        float g = 1.0f / (1.0f + expf(-(__half2float(mwlh[idx]) + bm[d0 + tx])));
        float l  = __half2float(localh[idx]);
        float gl = __half2float(globh[idx]);
        mixedh[idx] = __float2half(g * l + (1.0f - g) * gl + bcv);
    }
}

__global__ void h_copy(const float* __restrict__ in, __half* __restrict__ out, long n) {
    long idx = (long)blockIdx.x * 256 + threadIdx.x;
    if (idx < n) out[idx] = __float2half(in[idx]);
}

__global__ void __launch_bounds__(256) bcast_k(float* xt) {
    __shared__ float a[SS];
    float res[32], nv[32];
    float* g = xt + (long)blockIdx.x * SS;
    int tid = threadIdx.x;
    #pragma unroll
    for (int j = 0; j < 32; j++) { a[tid + 256 * j] = g[tid + 256 * j]; res[j] = 0.0f; }
    __syncthreads();
    for (int s = 1; s < SS; s <<= 1) {
        #pragma unroll
        for (int j = 0; j < 32; j++) {
            int i = tid + 256 * j;
            nv[j] = a[i] + 0.5f * (a[(i - s) & (SS - 1)] + a[(i + s) & (SS - 1)]);
        }
        __syncthreads();
        #pragma unroll
        for (int j = 0; j < 32; j++) { int i = tid + 256 * j; a[i] = nv[j]; res[j] += nv[j]; }
        __syncthreads();
    }
    const float inv = 1.0f / 14.0f;
    #pragma unroll
    for (int j = 0; j < 32; j++) g[tid + 256 * j] = res[j] * inv;
}

__global__ void wc_reorder(const float* __restrict__ Wc, __half* __restrict__ Wc2h) {
    long idx = (long)blockIdx.x * 256 + threadIdx.x;
    int o = (int)(idx >> 12);
    int rem = (int)(idx & 4095);
    int k = rem >> 10;
    int d = rem & 1023;
    Wc2h[idx] = __float2half(Wc[(long)o * 4096 + d * 4 + k]);
}

__global__ void build_gth(const float* __restrict__ gm, __half* __restrict__ gth) {
    long idx = (long)blockIdx.x * 256 + threadIdx.x;
    int b = (int)(idx >> 17);
    int rem = (int)(idx & 131071);
    int row = rem >> 10;
    int d = rem & 1023;
    gth[(long)b * 256 * 1024 + (long)(128 + row) * 1024 + d] = __float2half(gm[(long)row * 1024 + d]);
}

__device__ __forceinline__ float blk_max(float v, float* red) {
    int tid = threadIdx.x;
    #pragma unroll
    for (int o = 16; o; o >>= 1) v = fmaxf(v, __shfl_xor_sync(0xffffffffu, v, o));
    if ((tid & 31) == 0) red[tid >> 5] = v;
    __syncthreads();
    float m = red[0];
    #pragma unroll
    for (int i = 1; i < 8; i++) m = fmaxf(m, red[i]);
    return m;
}
__device__ __forceinline__ float blk_sum(float v, float* red) {
    int tid = threadIdx.x;
    #pragma unroll
    for (int o = 16; o; o >>= 1) v += __shfl_xor_sync(0xffffffffu, v, o);
    if ((tid & 31) == 0) red[tid >> 5] = v;
    __syncthreads();
    float s = 0.f;
    #pragma unroll
    for (int i = 0; i < 8; i++) s += red[i];
    return s;
}

__global__ void softmax256(const float* __restrict__ L, __half* __restrict__ Lh) {
    __shared__ float red[8];
    const float* r = L + (long)blockIdx.x * 256;
    int tid = threadIdx.x;
    float v = r[tid];
    float m = blk_max(v, red);
    __syncthreads();
    float e = expf(v - m);
    float s = blk_sum(e, red);
    Lh[(long)blockIdx.x * 256 + tid] = __float2half(e / s);
}

__global__ void softmax_causal2(const __half* __restrict__ Ddh, const __half* __restrict__ Doh,
                                __half* __restrict__ Ph) {
    __shared__ float red[8];
    int q = blockIdx.x, w = blockIdx.y;
    int b = w / 7, n = w % 7;
    __half* out = Ph + ((long)w * WLEN + q) * WLEN;
    int rb = ((q >> 7) + 1) << 7;
    int tid = threadIdx.x;
    float vA[4], vB[4];
    int cA = 0, cB = 0;
    float m = -1e30f;
    const __half hz = __float2half(0.0f);

    if (q < 1024) {
        const __half* src = Ddh + (((long)(b * 8 + n)) * 1024 + q) * 1024;
        int len = q + 1;
        for (int i = tid; i < len; i += 256) { vA[cA] = __half2float(src[i]); m = fmaxf(m, vA[cA]); cA++; }
        m = blk_max(m, red);
        __syncthreads();
        float s = 0.f;
        #pragma unroll
        for (int j = 0; j < 4; j++) if (j < cA) { vA[j] = expf(vA[j] - m); s += vA[j]; }
        s = blk_sum(s, red);
        float inv = 1.0f / s;
        cA = 0;
        for (int i = tid; i < len; i += 256) out[i] = __float2half(vA[cA++] * inv);
        for (int i = len + tid; i < rb; i += 256) out[i] = hz;
    } else {
        int q2 = q - 1024;
        const __half* srcA = Doh + (((long)(b * 7 + n)) * 1024 + q2) * 1024;
        const __half* srcB = Ddh + (((long)(b * 8 + n + 1)) * 1024 + q2) * 1024;
        int lenB = q2 + 1;
        for (int i = tid; i < 1024; i += 256) { vA[cA] = __half2float(srcA[i]); m = fmaxf(m, vA[cA]); cA++; }
        for (int i = tid; i < lenB; i += 256) { vB[cB] = __half2float(srcB[i]); m = fmaxf(m, vB[cB]); cB++; }
        m = blk_max(m, red);
        __syncthreads();
        float s = 0.f;
        #pragma unroll
        for (int j = 0; j < 4; j++) if (j < cA) { vA[j] = expf(vA[j] - m); s += vA[j]; }
        #pragma unroll
        for (int j = 0; j < 4; j++) if (j < cB) { vB[j] = expf(vB[j] - m); s += vB[j]; }
        s = blk_sum(s, red);
        float inv = 1.0f / s;
        cA = 0; cB = 0;
        for (int i = tid; i < 1024; i += 256) out[i] = __float2half(vA[cA++] * inv);
        for (int i = tid; i < lenB; i += 256) out[1024 + i] = __float2half(vB[cB++] * inv);
        for (int i = 1024 + lenB + tid; i < rb; i += 256) out[i] = hz;
    }
}

__global__ void combine_local(const __half* __restrict__ Oscrh, __half* __restrict__ localh) {
    long idx = (long)blockIdx.x * 256 + threadIdx.x;
    int d = (int)(idx & 1023);
    long pd = idx >> 10;
    int p = (int)(pd & (SS - 1));
    int b = (int)(pd >> 13);
    int nhi = p >> 10;
    int n1 = min(nhi, NWIN - 1);
    int n0 = max(nhi - 1, 0);
    float acc = 0.f, wsum = 0.f;
    for (int n = n0; n <= n1; n++) {
        int q = p - (n << 10);
        float tri = 0.5f + q * (1.0f / 2047.0f);
        acc  += __half2float(Oscrh[(((long)(b * NWIN + n)) * WLEN + q) * DD + d]) * tri;
        wsum += tri;
    }
    localh[idx] = __float2half(acc / (wsum + 1e-6f));
}

extern "C" void kernel_launch(void* const* d_in, const int* in_sizes, int n_in,
                              void* d_out, int out_size) {
    const float* x  = (const float*)d_in[0];
    const float* gm = (const float*)d_in[1];
    const float* Wc = (const float*)d_in[2];
    const float* bc = (const float*)d_in[3];
    const float* Wm = (const float*)d_in[4];
    const float* bm = (const float*)d_in[5];
    const float* Wo = (const float*)d_in[6];
    const float* bo = (const float*)d_in[7];
    float* out = (float*)d_out;

    __half *xh, *Wc2h, *gth, *lg2h, *Ph, *localh, *globh, *mixedh, *Wmh, *Woh, *Ddh, *Doh, *Oscrh;
    float *lg2, *xt;
    cudaGetSymbolAddress((void**)&xh,     g_xh);
    cudaGetSymbolAddress((void**)&Wc2h,   g_Wc2h);
    cudaGetSymbolAddress((void**)&gth,    g_gth);
    cudaGetSymbolAddress((void**)&lg2h,   g_lg2h);
    cudaGetSymbolAddress((void**)&Ph,     g_Ph);
    cudaGetSymbolAddress((void**)&localh, g_localh);
    cudaGetSymbolAddress((void**)&globh,  g_globh);
    cudaGetSymbolAddress((void**)&mixedh, g_mixedh);
    cudaGetSymbolAddress((void**)&Wmh,    g_Wmh);
    cudaGetSymbolAddress((void**)&Woh,    g_Woh);
    cudaGetSymbolAddress((void**)&Ddh,    g_Ddh);
    cudaGetSymbolAddress((void**)&Doh,    g_Doh);
    cudaGetSymbolAddress((void**)&Oscrh,  g_Oscrh);
    cudaGetSymbolAddress((void**)&lg2,    g_lg2);
    cudaGetSymbolAddress((void**)&xt,     g_xt);

    cudaFuncSetAttribute(gemm_h<1>, cudaFuncAttributeMaxDynamicSharedMemorySize, SMEM_TB1);
    cudaFuncSetAttribute(gemm_h<0>, cudaFuncAttributeMaxDynamicSharedMemorySize, SMEM_TB0);

    static cudaStream_t s2 = nullptr;
    static cudaEvent_t ev1 = nullptr, ev2 = nullptr;
    if (!s2) {
        cudaStreamCreateWithFlags(&s2, cudaStreamNonBlocking);
        cudaEventCreateWithFlags(&ev1, cudaEventDisableTiming);
        cudaEventCreateWithFlags(&ev2, cudaEventDisableTiming);
    }

    const float isq = 1.0f / 32.0f;
    const long SD = (long)SS * DD;
    __half* mwlh = Ph;   // reuse P buffer for mw logits

    prep_x<<<dim3(32, 256, 2), dim3(32, 8)>>>(x, xh, xt);
    cudaEventRecord(ev1, 0);
    cudaStreamWaitEvent(s2, ev1, 0);

    // ---------- branch B (s2): memory-bound work + global path ----------
    wc_reorder<<<16384, 256, 0, s2>>>(Wc, Wc2h);
    build_gth<<<1024, 256, 0, s2>>>(gm, gth);
    h_copy<<<(2 * 1024 * 1024 + 255) / 256, 256, 0, s2>>>(Wm, Wmh, 2L * 1024 * 1024);
    h_copy<<<(1024 * 1024 + 255) / 256, 256, 0, s2>>>(Wo, Woh, 1024L * 1024);
    bcast_k<<<BB * DD, 256, 0, s2>>>(xt);
    {   // comp: gth rows 0..127 = xh_view(128x4096) @ Wc2h^T + bc
        GP p{}; p.A = xh; p.B = Wc2h; p.Ch = gth; p.bias = bc;
        p.lda = 4096; p.ldb = 4096; p.ldc = 1024;
        p.sA = SD; p.sC = 256L * 1024;
        p.K = 4096; p.alpha = 1.0f;
        gemm_h<1><<<dim3(8, 1, 2), 128, SMEM_TB1, s2>>>(p);
    }
    {   // logits = xh @ gth^T / 32
        GP p{}; p.A = xh; p.B = gth; p.Cf = lg2;
        p.lda = 1024; p.ldb = 1024; p.ldc = 256;
        p.sA = SD; p.sB = 256L * 1024; p.sC = (long)SS * 256;
        p.K = 1024; p.alpha = isq;
        gemm_h<1><<<dim3(2, 64, 2), 128, SMEM_TB1, s2>>>(p);
    }
    softmax256<<<BB * SS, 256, 0, s2>>>(lg2, lg2h);
    {   // glob = attn @ gt (half out)
        GP p{}; p.A = lg2h; p.B = gth; p.Ch = globh;
        p.lda = 256; p.ldb = 1024; p.ldc = 1024;
        p.sA = (long)SS * 256; p.sB = 256L * 1024; p.sC = SD;
        p.K = 256; p.alpha = 1.0f;
        gemm_h<0><<<dim3(8, 64, 2), 128, SMEM_TB0, s2>>>(p);
    }
    cudaEventRecord(ev2, s2);

    // ---------- branch A (default stream): window path ----------
    {   // combined unique score blocks
        GP p{}; p.A = xh; p.B = xh; p.Ch = Ddh; p.Ch2 = Doh;
        p.lda = 1024; p.ldb = 1024; p.ldc = 1024;
        p.sC = 1024L * 1024;
        p.K = 1024; p.alpha = isq;
        p.mode = 4;
        gemm_h<1><<<dim3(8, 8, BB * 8 + BB * 7), 128, SMEM_TB1>>>(p);
    }
    softmax_causal2<<<dim3(WLEN, NBW), 256>>>(Ddh, Doh, Ph);
    {   // out_w = P @ w
        GP p{}; p.A = Ph; p.B = xh; p.Ch = Oscrh;
        p.lda = WLEN; p.ldb = 1024; p.ldc = 1024;
        p.sA = (long)WLEN * WLEN; p.sC = (long)WLEN * DD;
        p.K = WLEN; p.alpha = 1.0f;
        p.winB = 1; p.klimit = 1;
        gemm_h<0><<<dim3(8, 16, NBW), 128, SMEM_TB0>>>(p);
    }
    combine_local<<<65536, 256>>>(Oscrh, localh);

    // ---------- join ----------
    cudaStreamWaitEvent(0, ev2, 0);

    {   // mw logits = [local|glob] @ Wm^T (dual-A, K=2048, half out into Ph reuse)
        GP p{}; p.A = localh; p.A2 = globh; p.B = Wmh; p.Ch = mwlh;
        p.lda = 1024; p.ldb = 2048; p.ldc = 1024;
        p.K = 2048; p.kSplit = 1024; p.alpha = 1.0f;
        gemm_h<1><<<dim3(8, 128, 1), 128, SMEM_TB1>>>(p);
    }
    transpose_mix<<<dim3(256, 32, 2), dim3(32, 8)>>>(xt, mwlh, bm, localh, globh, mixedh);

    {   // out = mixed @ Wo^T + bo
        GP p{}; p.A = mixedh; p.B = Woh; p.Cf = out; p.bias = bo;
        p.lda = 1024; p.ldb = 1024; p.ldc = 1024;
        p.K = 1024; p.alpha = 1.0f;
        gemm_h<1><<<dim3(8, 128, 1), 128, SMEM_TB1>>>(p);
    }
}

// round 17
// speedup vs baseline: 1.1088x; 1.0365x over previous
#include <cuda_runtime.h>
#include <cuda_fp16.h>
#include <mma.h>
#include <math.h>
#include <stdint.h>

using namespace nvcuda;

#define BB   2
#define SS   8192
#define DD   1024
#define NWIN 7
#define NBW  14
#define WLEN 2048
#define GG   128

// ---------------- static scratch ----------------
__device__ __half g_xh    [(size_t)BB * SS * DD];
__device__ __half g_Wc2h  [(size_t)DD * 4096];
__device__ __half g_gth   [(size_t)BB * 256 * DD];
__device__ __half g_lg2h  [(size_t)BB * SS * 256];
__device__ __half g_localh[(size_t)BB * SS * DD];
__device__ __half g_globh [(size_t)BB * SS * DD];
__device__ __half g_mixedh[(size_t)BB * SS * DD];
__device__ __half g_Wmh   [(size_t)DD * 2 * DD];
__device__ __half g_Woh   [(size_t)DD * DD];
__device__ __half g_Ddh   [(size_t)BB * 8 * 1024 * 1024];  // exp diag blocks; reused as mw logits
__device__ __half g_Doh   [(size_t)BB * 7 * 1024 * 1024];  // exp off-diag blocks
__device__ __half g_Oscrh [(size_t)NBW * WLEN * DD];
__device__ float  g_lg2   [(size_t)BB * SS * 256];
__device__ float  g_xt    [(size_t)BB * DD * SS];
__device__ float  g_rn    [(size_t)BB * SS];               // self-score per token
__device__ float  g_inv   [(size_t)NBW * WLEN];            // 1/rowsum per window row

struct GP {
    const __half* A;
    const __half* A2;
    const __half* B;
    float*  Cf;
    __half* Ch;
    __half* Ch2;          // mode-4 off-diag target
    const float* bias;    // per-column bias; for EXP=1: rn pointer
    int lda, ldb, ldc;
    long sA, sB, sC;
    int K, kSplit;
    float alpha;
    int mode;             // 0 normal, 4 combined scores, 5 PV from exp blocks
    int winB;
    int causal, klimit;
};

__device__ __forceinline__ long window_off(int z) {
    return (long)(z / NWIN) * ((long)SS * DD) + (long)(z % NWIN) * (1024L * DD);
}

__device__ __forceinline__ void cp16(void* smem, const void* g) {
    uint32_t s = (uint32_t)__cvta_generic_to_shared(smem);
    asm volatile("cp.async.ca.shared.global [%0], [%1], 16;\n" :: "r"(s), "l"(g));
}
__device__ __forceinline__ void cp_commit() { asm volatile("cp.async.commit_group;\n"); }
template<int N> __device__ __forceinline__ void cp_wait() { asm volatile("cp.async.wait_group %0;\n" :: "n"(N)); }

// TB=1: C = A*B^T ; TB=0: C = A*B. fp16 operands, fp32 accumulate.
// EXP=1: epilogue stores exp(v - rn[row]) with causal mask (score GEMM only).
template<int TB, int EXP>
__global__ void __launch_bounds__(128) gemm_h(GP p) {
    constexpr int BM = 128, BN = 128, BK = 32, ST = 4;
    constexpr int ALD = 40;
    constexpr int BLD = TB ? 40 : 136;
    constexpr int BROWS = TB ? 128 : 32;
    constexpr int ASTG = BM * ALD;
    constexpr int BSTG = BROWS * BLD;

    int i0 = blockIdx.y * BM;
    int j0 = blockIdx.x * BN;
    if (p.causal && j0 > i0) return;
    int z = blockIdx.z;
    const __half* A;
    const __half* Bm;
    const __half* A2loc = p.A2;
    int ksp = p.kSplit;
    __half* ChBase = p.Ch;
    int zc = z;
    long rnBase = 0;
    int isDiag = 0;
    if (p.mode == 4) {
        if (z < BB * 8) {
            if (j0 > i0) return;
            int b = z >> 3, n = z & 7;
            long o = (long)b * ((long)SS * DD) + (long)n * (1024L * DD);
            A = p.A + o; Bm = p.B + o;
            if constexpr (EXP) { rnBase = (long)b * SS + (long)n * 1024; isDiag = 1; }
        } else {
            int zz = z - BB * 8;
            int b = zz / 7, n = zz % 7;
            A  = p.A + (long)b * ((long)SS * DD) + (long)(n + 1) * (1024L * DD);
            Bm = p.B + (long)b * ((long)SS * DD) + (long)n * (1024L * DD);
            ChBase = p.Ch2; zc = zz;
            if constexpr (EXP) { rnBase = (long)b * SS + (long)(n + 1) * 1024; }
        }
    }
    else if (p.mode == 5) {
        int b = z / 7, n = z % 7;
        if (i0 < 1024) {
            A = p.A + (long)(b * 8 + n) * 1048576;       // Ddh diag block, rows=q
            A2loc = nullptr;
        } else {
            A = p.A2 + (long)(b * 7 + n) * 1048576 - 1048576;     // Doh, rows offset -1024
            A2loc = p.A + (long)(b * 8 + n + 1) * 1048576 - 1048576; // Ddh[n+1], cols>=1024
            ksp = 1024;
        }
        Bm = p.B + window_off(z);
    }
    else { A = p.A + z * p.sA; Bm = p.B + (p.winB ? window_off(z) : z * p.sB); }
    float*  Cf = p.Cf ? p.Cf + z * p.sC : nullptr;
    __half* Ch = ChBase ? ChBase + zc * p.sC : nullptr;
    int K  = p.klimit ? min(p.K, i0 + BM) : p.K;
    int KT = K / BK;

    extern __shared__ __half smem_h[];
    __half* Asm = smem_h;
    __half* Bsm = smem_h + ST * ASTG;

    int tid = threadIdx.x;
    int ar = tid >> 2, ac = (tid & 3) << 3;
    int br, bcd;
    if (TB) { br = tid >> 2;  bcd = (tid & 3) << 3;  }
    else    { br = tid >> 4;  bcd = (tid & 15) << 3; }

    auto load_tile = [&](int kt, int sl) {
        long acol = (long)kt * BK;
        const __half* Ag;
        if (A2loc && acol >= ksp)
            Ag = A2loc + (long)(i0 + ar) * p.lda + (acol - ksp) + ac;
        else
            Ag = A + (long)(i0 + ar) * p.lda + acol + ac;
        __half* As = Asm + sl * ASTG;
        #pragma unroll
        for (int q = 0; q < 4; q++)
            cp16(&As[(ar + 32 * q) * ALD + ac], Ag + (long)(32 * q) * p.lda);
        __half* Bs = Bsm + sl * BSTG;
        if (TB) {
            const __half* Bg = Bm + (long)(j0 + br) * p.ldb + acol + bcd;
            #pragma unroll
            for (int q = 0; q < 4; q++)
                cp16(&Bs[(br + 32 * q) * BLD + bcd], Bg + (long)(32 * q) * p.ldb);
        } else {
            const __half* Bg = Bm + (acol + br) * (long)p.ldb + j0 + bcd;
            #pragma unroll
            for (int q = 0; q < 4; q++)
                cp16(&Bs[(br + 8 * q) * BLD + bcd], Bg + (long)(8 * q) * p.ldb);
        }
    };

    #pragma unroll
    for (int s = 0; s < ST - 1; s++) {
        if (s < KT) load_tile(s, s);
        cp_commit();
    }

    int wid = tid >> 5;
    int lane = tid & 31;
    int wr  = (wid & 1) * 64;
    int wc  = (wid >> 1) * 64;

    wmma::fragment<wmma::accumulator, 16, 16, 16, float> acc[4][4];
    #pragma unroll
    for (int i = 0; i < 4; i++)
        #pragma unroll
        for (int j = 0; j < 4; j++) wmma::fill_fragment(acc[i][j], 0.0f);

    for (int kt = 0; kt < KT; kt++) {
        cp_wait<ST - 2>();
        __syncthreads();
        if (kt + ST - 1 < KT) load_tile(kt + ST - 1, (kt + ST - 1) & (ST - 1));
        cp_commit();

        int sl = kt & (ST - 1);
        const __half* As = Asm + sl * ASTG;
        const __half* Bs = Bsm + sl * BSTG;

        #pragma unroll
        for (int ks = 0; ks < 2; ks++) {
            wmma::fragment<wmma::matrix_a, 16, 16, 16, __half, wmma::row_major> af[4];
            #pragma unroll
            for (int i = 0; i < 4; i++)
                wmma::load_matrix_sync(af[i], &As[(wr + i * 16) * ALD + ks * 16], ALD);
            #pragma unroll
            for (int j = 0; j < 4; j++) {
                if (TB) {
                    wmma::fragment<wmma::matrix_b, 16, 16, 16, __half, wmma::col_major> bf;
                    wmma::load_matrix_sync(bf, &Bs[(wc + j * 16) * BLD + ks * 16], BLD);
                    #pragma unroll
                    for (int i = 0; i < 4; i++)
                        wmma::mma_sync(acc[i][j], af[i], bf, acc[i][j]);
                } else {
                    wmma::fragment<wmma::matrix_b, 16, 16, 16, __half, wmma::row_major> bf;
                    wmma::load_matrix_sync(bf, &Bs[(ks * 16) * BLD + wc + j * 16], BLD);
                    #pragma unroll
                    for (int i = 0; i < 4; i++)
                        wmma::mma_sync(acc[i][j], af[i], bf, acc[i][j]);
                }
            }
        }
    }

    // ---- staged epilogue ----
    __syncthreads();
    float* stg = reinterpret_cast<float*>(smem_h) + wid * (64 * 72);
    #pragma unroll
    for (int i = 0; i < 4; i++)
        #pragma unroll
        for (int j = 0; j < 4; j++)
            wmma::store_matrix_sync(&stg[(i * 16) * 72 + j * 16], acc[i][j], 72, wmma::mem_row_major);
    __syncwarp();

    int rbase = i0 + wr;
    int cbase = j0 + wc;
    #pragma unroll
    for (int rr = 0; rr < 64; rr += 8) {
        int r = rr + (lane >> 2);
        int c = (lane & 3) << 4;
        long gro = (long)(rbase + r) * p.ldc + cbase + c;
        float rv;
        if constexpr (EXP) rv = p.bias[rnBase + rbase + r];
        #pragma unroll
        for (int q = 0; q < 4; q++) {
            float4 v = *(float4*)&stg[r * 72 + c + q * 4];
            v.x *= p.alpha; v.y *= p.alpha; v.z *= p.alpha; v.w *= p.alpha;
            if constexpr (EXP) {
                int rowIdx = rbase + r;
                int col0 = cbase + c + q * 4;
                v.x = __expf(v.x - rv);
                v.y = __expf(v.y - rv);
                v.z = __expf(v.z - rv);
                v.w = __expf(v.w - rv);
                if (isDiag) {
                    if (col0 + 0 > rowIdx) v.x = 0.0f;
                    if (col0 + 1 > rowIdx) v.y = 0.0f;
                    if (col0 + 2 > rowIdx) v.z = 0.0f;
                    if (col0 + 3 > rowIdx) v.w = 0.0f;
                }
            } else {
                if (p.bias) {
                    float4 b = *(const float4*)&p.bias[cbase + c + q * 4];
                    v.x += b.x; v.y += b.y; v.z += b.z; v.w += b.w;
                }
            }
            if (Cf) *(float4*)&Cf[gro + q * 4] = v;
            if (Ch) {
                *(__half2*)&Ch[gro + q * 4]     = __floats2half2_rn(v.x, v.y);
                *(__half2*)&Ch[gro + q * 4 + 2] = __floats2half2_rn(v.z, v.w);
            }
        }
    }
}

#define SMEM_TB1 ((4 * (128 * 40) + 4 * (128 * 40)) * 2)
#define SMEM_TB0 ((4 * (128 * 40) + 4 * (32 * 136)) * 2)

// ---------------- elementwise ----------------
__global__ void prep_x(const float* __restrict__ x, __half* __restrict__ xh, float* __restrict__ xt) {
    __shared__ float t[32][33];
    int b = blockIdx.z;
    long bo = (long)b * SS * DD;
    int s0 = blockIdx.y * 32, d0 = blockIdx.x * 32;
    int tx = threadIdx.x, ty = threadIdx.y;
    #pragma unroll
    for (int k = 0; k < 32; k += 8) {
        long gi = bo + (long)(s0 + ty + k) * DD + d0 + tx;
        float v = x[gi];
        t[ty + k][tx] = v;
        xh[gi] = __float2half(v);
    }
    __syncthreads();
    #pragma unroll
    for (int k = 0; k < 32; k += 8)
        xt[(long)b * DD * SS + (long)(d0 + ty + k) * SS + s0 + tx] = t[tx][ty + k];
}

__global__ void transpose_mix(const float* __restrict__ xt, const __half* __restrict__ mwlh,
                              const float* __restrict__ bm, const __half* __restrict__ localh,
                              const __half* __restrict__ globh, __half* __restrict__ mixedh) {
    __shared__ float t[32][33];
    int b = blockIdx.z;
    int s0 = blockIdx.x * 32, d0 = blockIdx.y * 32;
    int tx = threadIdx.x, ty = threadIdx.y;
    #pragma unroll
    for (int k = 0; k < 32; k += 8)
        t[ty + k][tx] = xt[(long)b * DD * SS + (long)(d0 + ty + k) * SS + s0 + tx];
    __syncthreads();
    #pragma unroll
    for (int k = 0; k < 32; k += 8) {
        long idx = (long)b * SS * DD + (long)(s0 + ty + k) * DD + d0 + tx;
        float bcv = t[tx][ty + k];
        float g = 1.0f / (1.0f + expf(-(__half2float(mwlh[idx]) + bm[d0 + tx])));
        float l  = __half2float(localh[idx]);
        float gl = __half2float(globh[idx]);
        mixedh[idx] = __float2half(g * l + (1.0f - g) * gl + bcv);
    }
}

__global__ void h_copy(const float* __restrict__ in, __half* __restrict__ out, long n) {
    long idx = (long)blockIdx.x * 256 + threadIdx.x;
    if (idx < n) out[idx] = __float2half(in[idx]);
}

__global__ void __launch_bounds__(256) bcast_k(float* xt) {
    __shared__ float a[SS];
    float res[32], nv[32];
    float* g = xt + (long)blockIdx.x * SS;
    int tid = threadIdx.x;
    #pragma unroll
    for (int j = 0; j < 32; j++) { a[tid + 256 * j] = g[tid + 256 * j]; res[j] = 0.0f; }
    __syncthreads();
    for (int s = 1; s < SS; s <<= 1) {
        #pragma unroll
        for (int j = 0; j < 32; j++) {
            int i = tid + 256 * j;
            nv[j] = a[i] + 0.5f * (a[(i - s) & (SS - 1)] + a[(i + s) & (SS - 1)]);
        }
        __syncthreads();
        #pragma unroll
        for (int j = 0; j < 32; j++) { int i = tid + 256 * j; a[i] = nv[j]; res[j] += nv[j]; }
        __syncthreads();
    }
    const float inv = 1.0f / 14.0f;
    #pragma unroll
    for (int j = 0; j < 32; j++) g[tid + 256 * j] = res[j] * inv;
}

__global__ void wc_reorder(const float* __restrict__ Wc, __half* __restrict__ Wc2h) {
    long idx = (long)blockIdx.x * 256 + threadIdx.x;
    int o = (int)(idx >> 12);
    int rem = (int)(idx & 4095);
    int k = rem >> 10;
    int d = rem & 1023;
    Wc2h[idx] = __float2half(Wc[(long)o * 4096 + d * 4 + k]);
}

__global__ void build_gth(const float* __restrict__ gm, __half* __restrict__ gth) {
    long idx = (long)blockIdx.x * 256 + threadIdx.x;
    int b = (int)(idx >> 17);
    int rem = (int)(idx & 131071);
    int row = rem >> 10;
    int d = rem & 1023;
    gth[(long)b * 256 * 1024 + (long)(128 + row) * 1024 + d] = __float2half(gm[(long)row * 1024 + d]);
}

__device__ __forceinline__ float blk_max(float v, float* red) {
    int tid = threadIdx.x;
    #pragma unroll
    for (int o = 16; o; o >>= 1) v = fmaxf(v, __shfl_xor_sync(0xffffffffu, v, o));
    if ((tid & 31) == 0) red[tid >> 5] = v;
    __syncthreads();
    float m = red[0];
    #pragma unroll
    for (int i = 1; i < 8; i++) m = fmaxf(m, red[i]);
    return m;
}
__device__ __forceinline__ float blk_sum(float v, float* red) {
    int tid = threadIdx.x;
    #pragma unroll
    for (int o = 16; o; o >>= 1) v += __shfl_xor_sync(0xffffffffu, v, o);
    if ((tid & 31) == 0) red[tid >> 5] = v;
    __syncthreads();
    float s = 0.f;
    #pragma unroll
    for (int i = 0; i < 8; i++) s += red[i];
    return s;
}

// rn[b*SS+s] = ||x_s||^2 / 32  (the self-score, == row max of window logits)
__global__ void rownorm_k(const float* __restrict__ x, float* __restrict__ rn) {
    __shared__ float red[8];
    long row = blockIdx.x;
    const float4* r = (const float4*)(x + row * DD);
    float4 v = r[threadIdx.x];
    float s = v.x * v.x + v.y * v.y + v.z * v.z + v.w * v.w;
    s = blk_sum(s, red);
    if (threadIdx.x == 0) rn[row] = s * (1.0f / 32.0f);
}

// inv[w][q] = 1 / sum of stored exp over causal window row
__global__ void rowsum_k(const __half* __restrict__ Ddh, const __half* __restrict__ Doh,
                         float* __restrict__ inv) {
    __shared__ float red[8];
    int q = blockIdx.x, w = blockIdx.y;
    int b = w / 7, n = w % 7;
    int tid = threadIdx.x;
    float s = 0.f;
    if (q < 1024) {
        const __half* src = Ddh + ((long)(b * 8 + n) * 1024 + q) * 1024;
        for (int i = tid; i <= q; i += 256) s += __half2float(src[i]);
    } else {
        int q2 = q - 1024;
        const __half* srcA = Doh + ((long)(b * 7 + n) * 1024 + q2) * 1024;
        for (int i = tid; i < 1024; i += 256) s += __half2float(srcA[i]);
        const __half* srcB = Ddh + ((long)(b * 8 + n + 1) * 1024 + q2) * 1024;
        for (int i = tid; i <= q2; i += 256) s += __half2float(srcB[i]);
    }
    s = blk_sum(s, red);
    if (tid == 0) inv[(long)w * WLEN + q] = 1.0f / s;
}

__global__ void softmax256(const float* __restrict__ L, __half* __restrict__ Lh) {
    __shared__ float red[8];
    const float* r = L + (long)blockIdx.x * 256;
    int tid = threadIdx.x;
    float v = r[tid];
    float m = blk_max(v, red);
    __syncthreads();
    float e = expf(v - m);
    float s = blk_sum(e, red);
    Lh[(long)blockIdx.x * 256 + tid] = __float2half(e / s);
}

__global__ void combine_local(const __half* __restrict__ Oscrh, const float* __restrict__ inv,
                              __half* __restrict__ localh) {
    long idx = (long)blockIdx.x * 256 + threadIdx.x;
    int d = (int)(idx & 1023);
    long pd = idx >> 10;
    int p = (int)(pd & (SS - 1));
    int b = (int)(pd >> 13);
    int nhi = p >> 10;
    int n1 = min(nhi, NWIN - 1);
    int n0 = max(nhi - 1, 0);
    float acc = 0.f, wsum = 0.f;
    for (int n = n0; n <= n1; n++) {
        int q = p - (n << 10);
        float tri = 0.5f + q * (1.0f / 2047.0f);
        float iv = inv[(long)(b * NWIN + n) * WLEN + q];
        acc  += __half2float(Oscrh[(((long)(b * NWIN + n)) * WLEN + q) * DD + d]) * tri * iv;
        wsum += tri;
    }
    localh[idx] = __float2half(acc / (wsum + 1e-6f));
}

extern "C" void kernel_launch(void* const* d_in, const int* in_sizes, int n_in,
                              void* d_out, int out_size) {
    const float* x  = (const float*)d_in[0];
    const float* gm = (const float*)d_in[1];
    const float* Wc = (const float*)d_in[2];
    const float* bc = (const float*)d_in[3];
    const float* Wm = (const float*)d_in[4];
    const float* bm = (const float*)d_in[5];
    const float* Wo = (const float*)d_in[6];
    const float* bo = (const float*)d_in[7];
    float* out = (float*)d_out;

    __half *xh, *Wc2h, *gth, *lg2h, *localh, *globh, *mixedh, *Wmh, *Woh, *Ddh, *Doh, *Oscrh;
    float *lg2, *xt, *rn, *inv;
    cudaGetSymbolAddress((void**)&xh,     g_xh);
    cudaGetSymbolAddress((void**)&Wc2h,   g_Wc2h);
    cudaGetSymbolAddress((void**)&gth,    g_gth);
    cudaGetSymbolAddress((void**)&lg2h,   g_lg2h);
    cudaGetSymbolAddress((void**)&localh, g_localh);
    cudaGetSymbolAddress((void**)&globh,  g_globh);
    cudaGetSymbolAddress((void**)&mixedh, g_mixedh);
    cudaGetSymbolAddress((void**)&Wmh,    g_Wmh);
    cudaGetSymbolAddress((void**)&Woh,    g_Woh);
    cudaGetSymbolAddress((void**)&Ddh,    g_Ddh);
    cudaGetSymbolAddress((void**)&Doh,    g_Doh);
    cudaGetSymbolAddress((void**)&Oscrh,  g_Oscrh);
    cudaGetSymbolAddress((void**)&lg2,    g_lg2);
    cudaGetSymbolAddress((void**)&xt,     g_xt);
    cudaGetSymbolAddress((void**)&rn,     g_rn);
    cudaGetSymbolAddress((void**)&inv,    g_inv);

    cudaFuncSetAttribute(gemm_h<1,0>, cudaFuncAttributeMaxDynamicSharedMemorySize, SMEM_TB1);
    cudaFuncSetAttribute(gemm_h<1,1>, cudaFuncAttributeMaxDynamicSharedMemorySize, SMEM_TB1);
    cudaFuncSetAttribute(gemm_h<0,0>, cudaFuncAttributeMaxDynamicSharedMemorySize, SMEM_TB0);

    static cudaStream_t s2 = nullptr;
    static cudaEvent_t ev1 = nullptr, ev2 = nullptr;
    if (!s2) {
        cudaStreamCreateWithFlags(&s2, cudaStreamNonBlocking);
        cudaEventCreateWithFlags(&ev1, cudaEventDisableTiming);
        cudaEventCreateWithFlags(&ev2, cudaEventDisableTiming);
    }

    const float isq = 1.0f / 32.0f;
    const long SD = (long)SS * DD;
    __half* mwlh = Ddh;   // Ddh free after PV; reuse for mw logits (16.78M halves fits)

    rownorm_k<<<BB * SS, 256>>>(x, rn);
    prep_x<<<dim3(32, 256, 2), dim3(32, 8)>>>(x, xh, xt);
    cudaEventRecord(ev1, 0);
    cudaStreamWaitEvent(s2, ev1, 0);

    // ---------- branch B (s2): memory-bound work + global path ----------
    wc_reorder<<<16384, 256, 0, s2>>>(Wc, Wc2h);
    build_gth<<<1024, 256, 0, s2>>>(gm, gth);
    h_copy<<<(2 * 1024 * 1024 + 255) / 256, 256, 0, s2>>>(Wm, Wmh, 2L * 1024 * 1024);
    h_copy<<<(1024 * 1024 + 255) / 256, 256, 0, s2>>>(Wo, Woh, 1024L * 1024);
    bcast_k<<<BB * DD, 256, 0, s2>>>(xt);
    {   // comp: gth rows 0..127 = xh_view(128x4096) @ Wc2h^T + bc
        GP p{}; p.A = xh; p.B = Wc2h; p.Ch = gth; p.bias = bc;
        p.lda = 4096; p.ldb = 4096; p.ldc = 1024;
        p.sA = SD; p.sC = 256L * 1024;
        p.K = 4096; p.alpha = 1.0f;
        gemm_h<1,0><<<dim3(8, 1, 2), 128, SMEM_TB1, s2>>>(p);
    }
    {   // logits = xh @ gth^T / 32
        GP p{}; p.A = xh; p.B = gth; p.Cf = lg2;
        p.lda = 1024; p.ldb = 1024; p.ldc = 256;
        p.sA = SD; p.sB = 256L * 1024; p.sC = (long)SS * 256;
        p.K = 1024; p.alpha = isq;
        gemm_h<1,0><<<dim3(2, 64, 2), 128, SMEM_TB1, s2>>>(p);
    }
    softmax256<<<BB * SS, 256, 0, s2>>>(lg2, lg2h);
    {   // glob = attn @ gt (half out)
        GP p{}; p.A = lg2h; p.B = gth; p.Ch = globh;
        p.lda = 256; p.ldb = 1024; p.ldc = 1024;
        p.sA = (long)SS * 256; p.sB = 256L * 1024; p.sC = SD;
        p.K = 256; p.alpha = 1.0f;
        gemm_h<0,0><<<dim3(8, 64, 2), 128, SMEM_TB0, s2>>>(p);
    }
    cudaEventRecord(ev2, s2);

    // ---------- branch A (default stream): window path ----------
    {   // combined unique score blocks -> exp values (EXP epilogue, bias=rn)
        GP p{}; p.A = xh; p.B = xh; p.Ch = Ddh; p.Ch2 = Doh; p.bias = rn;
        p.lda = 1024; p.ldb = 1024; p.ldc = 1024;
        p.sC = 1024L * 1024;
        p.K = 1024; p.alpha = isq;
        p.mode = 4;
        gemm_h<1,1><<<dim3(8, 8, BB * 8 + BB * 7), 128, SMEM_TB1>>>(p);
    }
    rowsum_k<<<dim3(WLEN, NBW), 256>>>(Ddh, Doh, inv);
    {   // out_w_raw = exp @ w  (mode 5: split Dd/Do addressing, K limited)
        GP p{}; p.A = Ddh; p.A2 = Doh; p.B = xh; p.Ch = Oscrh;
        p.lda = 1024; p.ldb = 1024; p.ldc = 1024;
        p.sC = (long)WLEN * DD;
        p.K = WLEN; p.alpha = 1.0f;
        p.mode = 5; p.klimit = 1;
        gemm_h<0,0><<<dim3(8, 16, NBW), 128, SMEM_TB0>>>(p);
    }
    combine_local<<<65536, 256>>>(Oscrh, inv, localh);

    // ---------- join ----------
    cudaStreamWaitEvent(0, ev2, 0);

    {   // mw logits = [local|glob] @ Wm^T (dual-A, K=2048, half out into Ddh reuse)
        GP p{}; p.A = localh; p.A2 = globh; p.B = Wmh; p.Ch = mwlh;
        p.lda = 1024; p.ldb = 2048; p.ldc = 1024;
        p.K = 2048; p.kSplit = 1024; p.alpha = 1.0f;
        gemm_h<1,0><<<dim3(8, 128, 1), 128, SMEM_TB1>>>(p);
    }
    transpose_mix<<<dim3(256, 32, 2), dim3(32, 8)>>>(xt, mwlh, bm, localh, globh, mixedh);

    {   // out = mixed @ Wo^T + bo
        GP p{}; p.A = mixedh; p.B = Woh; p.Cf = out; p.bias = bo;
        p.lda = 1024; p.ldb = 1024; p.ldc = 1024;
        p.K = 1024; p.alpha = 1.0f;
        gemm_h<1,0><<<dim3(8, 128, 1), 128, SMEM_TB1>>>(p);
    }
}